// round 11
// baseline (speedup 1.0000x reference)
#include <cuda_runtime.h>
#include <cuda_bf16.h>
#include <math.h>
#include <stdint.h>

namespace {

constexpr int NPTS = 16384;

// ---------------- global scratch ----------------
__device__ float g_h2[NPTS * 1024];                       // [pt][k16][64] f32
__device__ __align__(16) uint32_t g_X0h[NPTS * 128];      // [pt][kp] bf16x2
__device__ __align__(16) uint32_t g_X0l[NPTS * 128];
__device__ __align__(16) uint32_t g_X1h[NPTS * 128];
__device__ __align__(16) uint32_t g_X1l[NPTS * 128];
__device__ float g_Xf[NPTS * 256];                        // f32 for kernelD
__device__ __align__(16) uint32_t g_dwh[NPTS * 256];      // [pt][kp of 512]
__device__ __align__(16) uint32_t g_dwl[NPTS * 256];
// converted weights, layout [n][kp]
__device__ __align__(16) uint32_t g_wx1h[256 * 128], g_wx1l[256 * 128];
__device__ __align__(16) uint32_t g_wx2h[256 * 128], g_wx2l[256 * 128];
__device__ __align__(16) uint32_t g_wpwh[128 * 256], g_wpwl[128 * 256];

__device__ __forceinline__ float elu1(float x) { return x > 0.f ? x : expm1f(x); }

__device__ __forceinline__ uint32_t packbf(float a, float b) {
    __nv_bfloat16 ha = __float2bfloat16_rn(a), hb = __float2bfloat16_rn(b);
    unsigned short ua = *reinterpret_cast<unsigned short*>(&ha);
    unsigned short ub = *reinterpret_cast<unsigned short*>(&hb);
    return (uint32_t)ua | ((uint32_t)ub << 16);
}
__device__ __forceinline__ void split2(float a, float b, uint32_t& hi, uint32_t& lo) {
    __nv_bfloat16 ha = __float2bfloat16_rn(a), hb = __float2bfloat16_rn(b);
    float ra = a - __bfloat162float(ha);
    float rb = b - __bfloat162float(hb);
    unsigned short ua = *reinterpret_cast<unsigned short*>(&ha);
    unsigned short ub = *reinterpret_cast<unsigned short*>(&hb);
    hi = (uint32_t)ua | ((uint32_t)ub << 16);
    lo = packbf(ra, rb);
}

// mma.sync m16n8k16 bf16 -> f32
__device__ __forceinline__ void mma16816(float* c, const uint32_t* a, const uint32_t* b) {
    asm("mma.sync.aligned.m16n8k16.row.col.f32.bf16.bf16.f32 "
        "{%0,%1,%2,%3}, {%4,%5,%6,%7}, {%8,%9}, {%0,%1,%2,%3};"
        : "+f"(c[0]), "+f"(c[1]), "+f"(c[2]), "+f"(c[3])
        : "r"(a[0]), "r"(a[1]), "r"(a[2]), "r"(a[3]), "r"(b[0]), "r"(b[1]));
}

// ============================ Kernel A ============================
constexpr int A_T = 512;
constexpr int A_W1  = 0;
constexpr int A_B1  = 192;
constexpr int A_B2  = 256;
constexpr int A_PLT = 320;     // 768
constexpr int A_W2  = 1088;    // 4096
constexpr int A_WC1 = 5184;    // 12544 (256 x pitch49)
constexpr int A_H1  = 17728;   // 16896 (256 x pitch66)
constexpr int A_SMEM = 34624;

__global__ void __launch_bounds__(A_T, 1)
kernelA(const float* __restrict__ rep_pt, const float* __restrict__ pts,
        const float* __restrict__ w1,  const float* __restrict__ b1,
        const float* __restrict__ w2,  const float* __restrict__ b2,
        const float* __restrict__ wc1, const float* __restrict__ bc1,
        const float* __restrict__ wx1, const float* __restrict__ wx2,
        const float* __restrict__ wpw)
{
    extern __shared__ float sm[];
    float* w1s  = sm + A_W1;
    float* b1s  = sm + A_B1;
    float* b2s  = sm + A_B2;
    float* plT  = sm + A_PLT;
    float* w2s  = sm + A_W2;
    float* wc1s = sm + A_WC1;
    float* h1   = sm + A_H1;

    const int t = threadIdx.x;

    // ---- weight conversion slice (global->global, no barrier needed) ----
    if (t < 384) {
        int i = blockIdx.x * 384 + t;
        if (i < 32768) {
            int kp = i >> 8, n = i & 255;
            float v0 = wx1[(2 * kp) * 256 + n], v1 = wx1[(2 * kp + 1) * 256 + n];
            uint32_t hi, lo; split2(v0, v1, hi, lo);
            g_wx1h[n * 128 + kp] = hi; g_wx1l[n * 128 + kp] = lo;
        } else if (i < 65536) {
            int j = i - 32768; int kp = j >> 8, n = j & 255;
            float v0 = wx2[(2 * kp) * 256 + n], v1 = wx2[(2 * kp + 1) * 256 + n];
            uint32_t hi, lo; split2(v0, v1, hi, lo);
            g_wx2h[n * 128 + kp] = hi; g_wx2l[n * 128 + kp] = lo;
        } else {
            int j = i - 65536; int kp = j >> 7, n = j & 127;
            float v0 = wpw[(2 * kp) * 128 + n], v1 = wpw[(2 * kp + 1) * 128 + n];
            uint32_t hi, lo; split2(v0, v1, hi, lo);
            g_wpwh[n * 256 + kp] = hi; g_wpwl[n * 256 + kp] = lo;
        }
    }

    for (int i = t; i < 192; i += A_T) w1s[i] = w1[i];
    if (t < 64) { b1s[t] = b1[t]; b2s[t] = b2[t]; }
    for (int i = t; i < 4096; i += A_T) w2s[i] = w2[i];
    for (int i = t; i < 256 * 48; i += A_T) {
        int o = i / 48, m = i - o * 48;
        wc1s[o * 49 + m] = wc1[i];
    }

    for (int b = 0; b < 4; b++) {
        const int pbase = blockIdx.x * 64 + b * 16;
        __syncthreads();

        for (int i = t; i < 768; i += A_T) {
            int g = i / 48, r = i - g * 48, d = r >> 4, k = r & 15;
            int pp = pbase + g;
            plT[i] = pts[(pp * 16 + k) * 3 + d] - rep_pt[pp * 3 + d];
        }
        __syncthreads();

        {   // A1
            int row = t >> 1, g = row >> 4, k = row & 15, cb = (t & 1) * 32;
            float p0 = plT[g * 48 + k];
            float p1 = plT[g * 48 + 16 + k];
            float p2 = plT[g * 48 + 32 + k];
            #pragma unroll
            for (int c = 0; c < 32; c++) {
                float a = b1s[cb + c] + p0 * w1s[cb + c] + p1 * w1s[64 + cb + c]
                          + p2 * w1s[128 + cb + c];
                h1[row * 66 + cb + c] = elu1(a);
            }
        }
        __syncthreads();

        {   // A2: h2 -> g_h2
            int tc = t & 15, tr = t >> 4;
            float acc[8][4];
            #pragma unroll
            for (int i = 0; i < 8; i++)
                #pragma unroll
                for (int c = 0; c < 4; c++) acc[i][c] = b2s[tc * 4 + c];
            #pragma unroll 8
            for (int j = 0; j < 64; j++) {
                float4 w = *(const float4*)&w2s[j * 64 + tc * 4];
                #pragma unroll
                for (int i = 0; i < 8; i++) {
                    float hv = h1[(tr * 8 + i) * 66 + j];
                    acc[i][0] += hv * w.x; acc[i][1] += hv * w.y;
                    acc[i][2] += hv * w.z; acc[i][3] += hv * w.w;
                }
            }
            #pragma unroll
            for (int i = 0; i < 8; i++) {
                int r = tr * 8 + i;
                float4 o = {elu1(acc[i][0]), elu1(acc[i][1]),
                            elu1(acc[i][2]), elu1(acc[i][3])};
                *(float4*)&g_h2[(size_t)pbase * 1024 + r * 64 + tc * 4] = o;
            }
        }

        {   // B: X0 -> hi/lo
            int g = t >> 5, lane = t & 31;
            float acc[8];
            #pragma unroll
            for (int q = 0; q < 8; q++) acc[q] = bc1[lane + 32 * q];
            const float* pg = plT + g * 48;
            #pragma unroll 8
            for (int m = 0; m < 48; m++) {
                float pv = pg[m];
                #pragma unroll
                for (int q = 0; q < 8; q++) acc[q] += pv * wc1s[(lane + 32 * q) * 49 + m];
            }
            const size_t ptr = (size_t)(pbase + g) * 128;
            #pragma unroll
            for (int q = 0; q < 8; q++) {
                float x = elu1(acc[q]);
                float y = __shfl_xor_sync(0xffffffffu, x, 1);
                if ((lane & 1) == 0) {
                    uint32_t hi, lo; split2(x, y, hi, lo);
                    int kp = (lane + 32 * q) >> 1;
                    g_X0h[ptr + kp] = hi;
                    g_X0l[ptr + kp] = lo;
                }
            }
        }
    }
}

// ============================ bf16 tensor GEMM (round-8 proven: 256 thr) ============================
template <int KP, int NT, int EPI>
__global__ void __launch_bounds__(256, 1)
bgemm(const uint32_t* __restrict__ Ah, const uint32_t* __restrict__ Al,
      const uint32_t* __restrict__ Wh, const uint32_t* __restrict__ Wl,
      const float* __restrict__ bias,
      const float* __restrict__ bng, const float* __restrict__ bnb,
      const float* __restrict__ bnm, const float* __restrict__ bnv,
      float* __restrict__ outf, uint32_t* __restrict__ outh, uint32_t* __restrict__ outl)
{
    constexpr int CH = KP / 8;
    constexpr int LDC = NT * 128;
    constexpr int KPO = NT * 64;

    __shared__ __align__(16) uint32_t S[2][2][2][1536];

    const int t = threadIdx.x;
    const int wid = t >> 5, lane = t & 31;
    const int warp_m = wid & 1, warp_n = wid >> 1;
    const int g = lane >> 2, tg = lane & 3;
    const int bm = (int)blockIdx.x / NT, bn = (int)blockIdx.x % NT;
    const int m0 = bm * 128, n0 = bn * 128;

    const int srow = t >> 1;
    const int h4 = (t & 1) * 4;
    const uint32_t* Asrc_h = Ah + (size_t)(m0 + srow) * KP + h4;
    const uint32_t* Asrc_l = Al + (size_t)(m0 + srow) * KP + h4;
    const uint32_t* Bsrc_h = Wh + (size_t)(n0 + srow) * KP + h4;
    const uint32_t* Bsrc_l = Wl + (size_t)(n0 + srow) * KP + h4;
    const int sdst = srow * 12 + h4;

    float acc[4][4][4];
    #pragma unroll
    for (int mt = 0; mt < 4; mt++)
        #pragma unroll
        for (int nt = 0; nt < 4; nt++)
            #pragma unroll
            for (int c = 0; c < 4; c++) acc[mt][nt][c] = 0.f;

    uint4 pa0, pa1, pb0, pb1;
    pa0 = *(const uint4*)&Asrc_h[0];
    pa1 = *(const uint4*)&Asrc_l[0];
    pb0 = *(const uint4*)&Bsrc_h[0];
    pb1 = *(const uint4*)&Bsrc_l[0];
    *(uint4*)&S[0][0][0][sdst] = pa0;
    *(uint4*)&S[0][0][1][sdst] = pa1;
    *(uint4*)&S[0][1][0][sdst] = pb0;
    *(uint4*)&S[0][1][1][sdst] = pb1;
    __syncthreads();

    if (CH > 1) {
        pa0 = *(const uint4*)&Asrc_h[8];
        pa1 = *(const uint4*)&Asrc_l[8];
        pb0 = *(const uint4*)&Bsrc_h[8];
        pb1 = *(const uint4*)&Bsrc_l[8];
    }

    for (int kc = 0; kc < CH; kc++) {
        const int cur = kc & 1;
        if (kc < CH - 1) {
            *(uint4*)&S[cur ^ 1][0][0][sdst] = pa0;
            *(uint4*)&S[cur ^ 1][0][1][sdst] = pa1;
            *(uint4*)&S[cur ^ 1][1][0][sdst] = pb0;
            *(uint4*)&S[cur ^ 1][1][1][sdst] = pb1;
        }
        if (kc < CH - 2) {
            const int koff = (kc + 2) * 8;
            pa0 = *(const uint4*)&Asrc_h[koff];
            pa1 = *(const uint4*)&Asrc_l[koff];
            pb0 = *(const uint4*)&Bsrc_h[koff];
            pb1 = *(const uint4*)&Bsrc_l[koff];
        }

        const uint32_t* sAh = &S[cur][0][0][0];
        const uint32_t* sAl = &S[cur][0][1][0];
        const uint32_t* sBh = &S[cur][1][0][0];
        const uint32_t* sBl = &S[cur][1][1][0];

        uint32_t ah[4][4], al[4][4], bh[4][2], bl[4][2];
        #pragma unroll
        for (int mt = 0; mt < 4; mt++) {
            const int r0 = (warp_m * 64 + mt * 16 + g) * 12;
            const int r8 = r0 + 96;
            ah[mt][0] = sAh[r0 + tg];     ah[mt][1] = sAh[r8 + tg];
            ah[mt][2] = sAh[r0 + tg + 4]; ah[mt][3] = sAh[r8 + tg + 4];
            al[mt][0] = sAl[r0 + tg];     al[mt][1] = sAl[r8 + tg];
            al[mt][2] = sAl[r0 + tg + 4]; al[mt][3] = sAl[r8 + tg + 4];
        }
        #pragma unroll
        for (int nt = 0; nt < 4; nt++) {
            const int c0 = (warp_n * 32 + nt * 8 + g) * 12;
            bh[nt][0] = sBh[c0 + tg]; bh[nt][1] = sBh[c0 + tg + 4];
            bl[nt][0] = sBl[c0 + tg]; bl[nt][1] = sBl[c0 + tg + 4];
        }
        #pragma unroll
        for (int mt = 0; mt < 4; mt++)
            #pragma unroll
            for (int nt = 0; nt < 4; nt++) {
                mma16816(acc[mt][nt], ah[mt], bh[nt]);
                mma16816(acc[mt][nt], ah[mt], bl[nt]);
                mma16816(acc[mt][nt], al[mt], bh[nt]);
            }
        __syncthreads();
    }

    #pragma unroll
    for (int nt = 0; nt < 4; nt++) {
        const int col = n0 + warp_n * 32 + nt * 8 + 2 * tg;
        const float b0 = bias[col], b1 = bias[col + 1];
        float sc0, sc1, mu0, mu1, be0, be1;
        if (EPI == 2) {
            sc0 = bng[col] * rsqrtf(bnv[col] + 1e-5f);
            sc1 = bng[col + 1] * rsqrtf(bnv[col + 1] + 1e-5f);
            mu0 = bnm[col]; mu1 = bnm[col + 1];
            be0 = bnb[col]; be1 = bnb[col + 1];
        }
        #pragma unroll
        for (int mt = 0; mt < 4; mt++) {
            const size_t row = (size_t)m0 + warp_m * 64 + mt * 16 + g;
            float c0 = acc[mt][nt][0] + b0, c1 = acc[mt][nt][1] + b1;
            float c2 = acc[mt][nt][2] + b0, c3 = acc[mt][nt][3] + b1;
            if (EPI == 0) {
                *(float2*)&outf[row * LDC + col]       = make_float2(c0, c1);
                *(float2*)&outf[(row + 8) * LDC + col] = make_float2(c2, c3);
            } else if (EPI == 1) {
                float x0 = elu1(c0), x1 = elu1(c1), x2 = elu1(c2), x3 = elu1(c3);
                uint32_t hi, lo;
                split2(x0, x1, hi, lo);
                outh[row * KPO + (col >> 1)] = hi;
                outl[row * KPO + (col >> 1)] = lo;
                split2(x2, x3, hi, lo);
                outh[(row + 8) * KPO + (col >> 1)] = hi;
                outl[(row + 8) * KPO + (col >> 1)] = lo;
            } else {
                float v0 = (elu1(c0) - mu0) * sc0 + be0;
                float v1 = (elu1(c1) - mu1) * sc1 + be1;
                float v2 = (elu1(c2) - mu0) * sc0 + be0;
                float v3 = (elu1(c3) - mu1) * sc1 + be1;
                *(float2*)&outf[row * LDC + col]       = make_float2(v0, v1);
                *(float2*)&outf[(row + 8) * LDC + col] = make_float2(v2, v3);
            }
        }
    }
}

// ============================ Kernel D (LDS-vectorized) ============================
// 16 points/CTA, 2 warps per point (channel halves), lane owns 2 channels.
// Xfs reads via float4 broadcast; wdw in [k][c][d] layout for float4 per channel.
constexpr int D_T = 256;
constexpr int D_WDWD = 0;        // 8192 floats: wdwD[(k*128 + c)*4 + d]
constexpr int D_XF   = 8192;     // 4096 floats: Xfs[16][256]
constexpr int D_SMEM = 12288;    // floats = 49152 B

__global__ void __launch_bounds__(D_T, 3)
kernelD(const float* __restrict__ fts, const float* __restrict__ wdw,
        const float* __restrict__ bdw)
{
    extern __shared__ float sm[];
    float* wdwD = sm + D_WDWD;
    float* Xfs  = sm + D_XF;

    const int t = threadIdx.x;
    const int pbase = blockIdx.x * 16;
    const int warp = t >> 5, lane = t & 31;

    // stage wdw [c][d][k] -> wdwD [k][c][d]  (coalesced reads, scattered smem writes)
    for (int i = t; i < 8192; i += D_T) {
        int c = i >> 6, d = (i >> 4) & 3, k = i & 15;
        wdwD[(k * 128 + c) * 4 + d] = wdw[i];
    }
    for (int i = t; i < 4096; i += D_T)
        Xfs[i] = g_Xf[(size_t)pbase * 256 + i];
    __syncthreads();

    const int wh = warp & 1;                  // channel half
    const int c0 = (wh * 32 + lane) * 2;      // channel pair base (even)

    float4 bA = *(const float4*)&bdw[c0 * 4];
    float4 bB = *(const float4*)&bdw[(c0 + 1) * 4];

    #pragma unroll
    for (int p = 0; p < 4; p++) {
        const int g = p * 4 + (warp >> 1);
        const size_t pt = pbase + g;

        const float* src = (c0 < 64) ? (g_h2 + pt * 1024 + c0)
                                     : (fts  + pt * 1024 + (c0 - 64));
        float2 fr[16];
        #pragma unroll
        for (int j = 0; j < 16; j++)
            fr[j] = *(const float2*)&src[j * 64];

        float dA[4] = {bA.x, bA.y, bA.z, bA.w};
        float dB[4] = {bB.x, bB.y, bB.z, bB.w};

        #pragma unroll
        for (int i = 0; i < 16; i++) {
            const float* xr = &Xfs[g * 256 + i * 16];
            float4 x0 = *(const float4*)&xr[0];
            float4 x1 = *(const float4*)&xr[4];
            float4 x2 = *(const float4*)&xr[8];
            float4 x3 = *(const float4*)&xr[12];
            float fx0, fx1;
            fx0  = x0.x * fr[0].x  + x0.y * fr[1].x  + x0.z * fr[2].x  + x0.w * fr[3].x;
            fx0 += x1.x * fr[4].x  + x1.y * fr[5].x  + x1.z * fr[6].x  + x1.w * fr[7].x;
            fx0 += x2.x * fr[8].x  + x2.y * fr[9].x  + x2.z * fr[10].x + x2.w * fr[11].x;
            fx0 += x3.x * fr[12].x + x3.y * fr[13].x + x3.z * fr[14].x + x3.w * fr[15].x;
            fx1  = x0.x * fr[0].y  + x0.y * fr[1].y  + x0.z * fr[2].y  + x0.w * fr[3].y;
            fx1 += x1.x * fr[4].y  + x1.y * fr[5].y  + x1.z * fr[6].y  + x1.w * fr[7].y;
            fx1 += x2.x * fr[8].y  + x2.y * fr[9].y  + x2.z * fr[10].y + x2.w * fr[11].y;
            fx1 += x3.x * fr[12].y + x3.y * fr[13].y + x3.z * fr[14].y + x3.w * fr[15].y;

            float4 wA = *(const float4*)&wdwD[(i * 128 + c0) * 4];
            float4 wB = *(const float4*)&wdwD[(i * 128 + c0 + 1) * 4];
            dA[0] += fx0 * wA.x; dA[1] += fx0 * wA.y;
            dA[2] += fx0 * wA.z; dA[3] += fx0 * wA.w;
            dB[0] += fx1 * wB.x; dB[1] += fx1 * wB.y;
            dB[2] += fx1 * wB.z; dB[3] += fx1 * wB.w;
        }

        uint32_t hi[4], lo[4];
        split2(dA[0], dA[1], hi[0], lo[0]);
        split2(dA[2], dA[3], hi[1], lo[1]);
        split2(dB[0], dB[1], hi[2], lo[2]);
        split2(dB[2], dB[3], hi[3], lo[3]);
        *(uint4*)&g_dwh[pt * 256 + c0 * 2] = make_uint4(hi[0], hi[1], hi[2], hi[3]);
        *(uint4*)&g_dwl[pt * 256 + c0 * 2] = make_uint4(lo[0], lo[1], lo[2], lo[3]);
    }
}

} // namespace

extern "C" void kernel_launch(void* const* d_in, const int* in_sizes, int n_in,
                              void* d_out, int out_size) {
    const float* rep_pt = (const float*)d_in[0];
    const float* pts    = (const float*)d_in[1];
    const float* fts    = (const float*)d_in[2];
    const float* w1     = (const float*)d_in[3];
    const float* b1     = (const float*)d_in[4];
    const float* w2     = (const float*)d_in[5];
    const float* b2     = (const float*)d_in[6];
    const float* wc1    = (const float*)d_in[7];
    const float* bc1    = (const float*)d_in[8];
    const float* wx1    = (const float*)d_in[9];
    const float* bx1    = (const float*)d_in[10];
    const float* wx2    = (const float*)d_in[11];
    const float* bx2    = (const float*)d_in[12];
    const float* wdw    = (const float*)d_in[13];
    const float* bdw    = (const float*)d_in[14];
    const float* wpw    = (const float*)d_in[15];
    const float* bpw    = (const float*)d_in[16];
    const float* bng    = (const float*)d_in[17];
    const float* bnb    = (const float*)d_in[18];
    const float* bnm    = (const float*)d_in[19];
    const float* bnv    = (const float*)d_in[20];
    float* out = (float*)d_out;

    static bool attr_done = false;
    if (!attr_done) {
        cudaFuncSetAttribute(kernelA, cudaFuncAttributeMaxDynamicSharedMemorySize,
                             A_SMEM * (int)sizeof(float));
        cudaFuncSetAttribute(kernelD, cudaFuncAttributeMaxDynamicSharedMemorySize,
                             D_SMEM * (int)sizeof(float));
        attr_done = true;
    }

    uint32_t *pX0h, *pX0l, *pX1h, *pX1l, *pdwh, *pdwl;
    uint32_t *pw1h, *pw1l, *pw2h, *pw2l, *pwph, *pwpl;
    float* pXf;
    cudaGetSymbolAddress((void**)&pX0h, g_X0h);
    cudaGetSymbolAddress((void**)&pX0l, g_X0l);
    cudaGetSymbolAddress((void**)&pX1h, g_X1h);
    cudaGetSymbolAddress((void**)&pX1l, g_X1l);
    cudaGetSymbolAddress((void**)&pXf,  g_Xf);
    cudaGetSymbolAddress((void**)&pdwh, g_dwh);
    cudaGetSymbolAddress((void**)&pdwl, g_dwl);
    cudaGetSymbolAddress((void**)&pw1h, g_wx1h);
    cudaGetSymbolAddress((void**)&pw1l, g_wx1l);
    cudaGetSymbolAddress((void**)&pw2h, g_wx2h);
    cudaGetSymbolAddress((void**)&pw2l, g_wx2l);
    cudaGetSymbolAddress((void**)&pwph, g_wpwh);
    cudaGetSymbolAddress((void**)&pwpl, g_wpwl);

    // A (with fused weight conversion): h2 (f32) + X0 (bf16 hi/lo)
    kernelA<<<NPTS / 64, A_T, A_SMEM * sizeof(float)>>>(
        rep_pt, pts, w1, b1, w2, b2, wc1, bc1, wx1, wx2, wpw);
    // B: X1 = elu(X0 @ wx1 + bx1) -> bf16 hi/lo
    bgemm<128, 2, 1><<<(NPTS / 128) * 2, 256>>>(
        pX0h, pX0l, pw1h, pw1l, bx1, nullptr, nullptr, nullptr, nullptr,
        nullptr, pX1h, pX1l);
    // C: Xf = X1 @ wx2 + bx2 -> f32
    bgemm<128, 2, 0><<<(NPTS / 128) * 2, 256>>>(
        pX1h, pX1l, pw2h, pw2l, bx2, nullptr, nullptr, nullptr, nullptr,
        pXf, nullptr, nullptr);
    // D: X-transform + depthwise -> dw bf16 hi/lo
    kernelD<<<NPTS / 16, D_T, D_SMEM * sizeof(float)>>>(fts, wdw, bdw);
    // E: out = BN(elu(dw @ wpw + bpw)) -> f32
    bgemm<256, 1, 2><<<NPTS / 128, 256>>>(
        pdwh, pdwl, pwph, pwpl, bpw, bng, bnb, bnm, bnv,
        out, nullptr, nullptr);
}

// round 12
// speedup vs baseline: 1.0885x; 1.0885x over previous
#include <cuda_runtime.h>
#include <cuda_bf16.h>
#include <math.h>
#include <stdint.h>

namespace {

constexpr int NPTS = 16384;

// ---------------- global scratch ----------------
__device__ float g_h2[NPTS * 1024];                       // [pt][k16][64] f32
__device__ __align__(16) uint32_t g_X0h[NPTS * 128];      // [pt][kp] bf16x2
__device__ __align__(16) uint32_t g_X0l[NPTS * 128];
__device__ __align__(16) uint32_t g_X1h[NPTS * 128];
__device__ __align__(16) uint32_t g_X1l[NPTS * 128];
__device__ float g_Xf[NPTS * 256];                        // f32 for kernelD
__device__ __align__(16) uint32_t g_dwh[NPTS * 256];      // [pt][kp of 512]
__device__ __align__(16) uint32_t g_dwl[NPTS * 256];
// converted weights, layout [n][kp]
__device__ __align__(16) uint32_t g_wx1h[256 * 128], g_wx1l[256 * 128];
__device__ __align__(16) uint32_t g_wx2h[256 * 128], g_wx2l[256 * 128];
__device__ __align__(16) uint32_t g_wpwh[128 * 256], g_wpwl[128 * 256];

__device__ __forceinline__ float elu1(float x) { return x > 0.f ? x : expm1f(x); }

__device__ __forceinline__ uint32_t packbf(float a, float b) {
    __nv_bfloat16 ha = __float2bfloat16_rn(a), hb = __float2bfloat16_rn(b);
    unsigned short ua = *reinterpret_cast<unsigned short*>(&ha);
    unsigned short ub = *reinterpret_cast<unsigned short*>(&hb);
    return (uint32_t)ua | ((uint32_t)ub << 16);
}
__device__ __forceinline__ void split2(float a, float b, uint32_t& hi, uint32_t& lo) {
    __nv_bfloat16 ha = __float2bfloat16_rn(a), hb = __float2bfloat16_rn(b);
    float ra = a - __bfloat162float(ha);
    float rb = b - __bfloat162float(hb);
    unsigned short ua = *reinterpret_cast<unsigned short*>(&ha);
    unsigned short ub = *reinterpret_cast<unsigned short*>(&hb);
    hi = (uint32_t)ua | ((uint32_t)ub << 16);
    lo = packbf(ra, rb);
}

// mma.sync m16n8k16 bf16 -> f32
__device__ __forceinline__ void mma16816(float* c, const uint32_t* a, const uint32_t* b) {
    asm("mma.sync.aligned.m16n8k16.row.col.f32.bf16.bf16.f32 "
        "{%0,%1,%2,%3}, {%4,%5,%6,%7}, {%8,%9}, {%0,%1,%2,%3};"
        : "+f"(c[0]), "+f"(c[1]), "+f"(c[2]), "+f"(c[3])
        : "r"(a[0]), "r"(a[1]), "r"(a[2]), "r"(a[3]), "r"(b[0]), "r"(b[1]));
}

__device__ __forceinline__ void l2pf(const float* p) {
    asm volatile("prefetch.global.L2 [%0];" :: "l"(p));
}

// ============================ Kernel A ============================
constexpr int A_T = 512;
constexpr int A_W1  = 0;
constexpr int A_B1  = 192;
constexpr int A_B2  = 256;
constexpr int A_PLT = 320;     // 768
constexpr int A_W2  = 1088;    // 4096
constexpr int A_WC1 = 5184;    // 12544 (256 x pitch49)
constexpr int A_H1  = 17728;   // 16896 (256 x pitch66)
constexpr int A_SMEM = 34624;

__global__ void __launch_bounds__(A_T, 1)
kernelA(const float* __restrict__ rep_pt, const float* __restrict__ pts,
        const float* __restrict__ w1,  const float* __restrict__ b1,
        const float* __restrict__ w2,  const float* __restrict__ b2,
        const float* __restrict__ wc1, const float* __restrict__ bc1,
        const float* __restrict__ wx1, const float* __restrict__ wx2,
        const float* __restrict__ wpw)
{
    extern __shared__ float sm[];
    float* w1s  = sm + A_W1;
    float* b1s  = sm + A_B1;
    float* b2s  = sm + A_B2;
    float* plT  = sm + A_PLT;
    float* w2s  = sm + A_W2;
    float* wc1s = sm + A_WC1;
    float* h1   = sm + A_H1;

    const int t = threadIdx.x;

    // ---- weight conversion slice (global->global, no barrier needed) ----
    if (t < 384) {
        int i = blockIdx.x * 384 + t;
        if (i < 32768) {
            int kp = i >> 8, n = i & 255;
            float v0 = wx1[(2 * kp) * 256 + n], v1 = wx1[(2 * kp + 1) * 256 + n];
            uint32_t hi, lo; split2(v0, v1, hi, lo);
            g_wx1h[n * 128 + kp] = hi; g_wx1l[n * 128 + kp] = lo;
        } else if (i < 65536) {
            int j = i - 32768; int kp = j >> 8, n = j & 255;
            float v0 = wx2[(2 * kp) * 256 + n], v1 = wx2[(2 * kp + 1) * 256 + n];
            uint32_t hi, lo; split2(v0, v1, hi, lo);
            g_wx2h[n * 128 + kp] = hi; g_wx2l[n * 128 + kp] = lo;
        } else {
            int j = i - 65536; int kp = j >> 7, n = j & 127;
            float v0 = wpw[(2 * kp) * 128 + n], v1 = wpw[(2 * kp + 1) * 128 + n];
            uint32_t hi, lo; split2(v0, v1, hi, lo);
            g_wpwh[n * 256 + kp] = hi; g_wpwl[n * 256 + kp] = lo;
        }
    }

    for (int i = t; i < 192; i += A_T) w1s[i] = w1[i];
    if (t < 64) { b1s[t] = b1[t]; b2s[t] = b2[t]; }
    for (int i = t; i < 4096; i += A_T) w2s[i] = w2[i];
    for (int i = t; i < 256 * 48; i += A_T) {
        int o = i / 48, m = i - o * 48;
        wc1s[o * 49 + m] = wc1[i];
    }

    for (int b = 0; b < 4; b++) {
        const int pbase = blockIdx.x * 64 + b * 16;
        __syncthreads();

        for (int i = t; i < 768; i += A_T) {
            int g = i / 48, r = i - g * 48, d = r >> 4, k = r & 15;
            int pp = pbase + g;
            plT[i] = pts[(pp * 16 + k) * 3 + d] - rep_pt[pp * 3 + d];
        }
        __syncthreads();

        {   // A1
            int row = t >> 1, g = row >> 4, k = row & 15, cb = (t & 1) * 32;
            float p0 = plT[g * 48 + k];
            float p1 = plT[g * 48 + 16 + k];
            float p2 = plT[g * 48 + 32 + k];
            #pragma unroll
            for (int c = 0; c < 32; c++) {
                float a = b1s[cb + c] + p0 * w1s[cb + c] + p1 * w1s[64 + cb + c]
                          + p2 * w1s[128 + cb + c];
                h1[row * 66 + cb + c] = elu1(a);
            }
        }
        __syncthreads();

        {   // A2: h2 -> g_h2
            int tc = t & 15, tr = t >> 4;
            float acc[8][4];
            #pragma unroll
            for (int i = 0; i < 8; i++)
                #pragma unroll
                for (int c = 0; c < 4; c++) acc[i][c] = b2s[tc * 4 + c];
            #pragma unroll 8
            for (int j = 0; j < 64; j++) {
                float4 w = *(const float4*)&w2s[j * 64 + tc * 4];
                #pragma unroll
                for (int i = 0; i < 8; i++) {
                    float hv = h1[(tr * 8 + i) * 66 + j];
                    acc[i][0] += hv * w.x; acc[i][1] += hv * w.y;
                    acc[i][2] += hv * w.z; acc[i][3] += hv * w.w;
                }
            }
            #pragma unroll
            for (int i = 0; i < 8; i++) {
                int r = tr * 8 + i;
                float4 o = {elu1(acc[i][0]), elu1(acc[i][1]),
                            elu1(acc[i][2]), elu1(acc[i][3])};
                *(float4*)&g_h2[(size_t)pbase * 1024 + r * 64 + tc * 4] = o;
            }
        }

        {   // B: X0 -> hi/lo
            int g = t >> 5, lane = t & 31;
            float acc[8];
            #pragma unroll
            for (int q = 0; q < 8; q++) acc[q] = bc1[lane + 32 * q];
            const float* pg = plT + g * 48;
            #pragma unroll 8
            for (int m = 0; m < 48; m++) {
                float pv = pg[m];
                #pragma unroll
                for (int q = 0; q < 8; q++) acc[q] += pv * wc1s[(lane + 32 * q) * 49 + m];
            }
            const size_t ptr = (size_t)(pbase + g) * 128;
            #pragma unroll
            for (int q = 0; q < 8; q++) {
                float x = elu1(acc[q]);
                float y = __shfl_xor_sync(0xffffffffu, x, 1);
                if ((lane & 1) == 0) {
                    uint32_t hi, lo; split2(x, y, hi, lo);
                    int kp = (lane + 32 * q) >> 1;
                    g_X0h[ptr + kp] = hi;
                    g_X0l[ptr + kp] = lo;
                }
            }
        }
    }
}

// ============================ bf16 tensor GEMM (round-8 proven: 256 thr) ============================
template <int KP, int NT, int EPI>
__global__ void __launch_bounds__(256, 1)
bgemm(const uint32_t* __restrict__ Ah, const uint32_t* __restrict__ Al,
      const uint32_t* __restrict__ Wh, const uint32_t* __restrict__ Wl,
      const float* __restrict__ bias,
      const float* __restrict__ bng, const float* __restrict__ bnb,
      const float* __restrict__ bnm, const float* __restrict__ bnv,
      float* __restrict__ outf, uint32_t* __restrict__ outh, uint32_t* __restrict__ outl)
{
    constexpr int CH = KP / 8;
    constexpr int LDC = NT * 128;
    constexpr int KPO = NT * 64;

    __shared__ __align__(16) uint32_t S[2][2][2][1536];

    const int t = threadIdx.x;
    const int wid = t >> 5, lane = t & 31;
    const int warp_m = wid & 1, warp_n = wid >> 1;
    const int g = lane >> 2, tg = lane & 3;
    const int bm = (int)blockIdx.x / NT, bn = (int)blockIdx.x % NT;
    const int m0 = bm * 128, n0 = bn * 128;

    const int srow = t >> 1;
    const int h4 = (t & 1) * 4;
    const uint32_t* Asrc_h = Ah + (size_t)(m0 + srow) * KP + h4;
    const uint32_t* Asrc_l = Al + (size_t)(m0 + srow) * KP + h4;
    const uint32_t* Bsrc_h = Wh + (size_t)(n0 + srow) * KP + h4;
    const uint32_t* Bsrc_l = Wl + (size_t)(n0 + srow) * KP + h4;
    const int sdst = srow * 12 + h4;

    float acc[4][4][4];
    #pragma unroll
    for (int mt = 0; mt < 4; mt++)
        #pragma unroll
        for (int nt = 0; nt < 4; nt++)
            #pragma unroll
            for (int c = 0; c < 4; c++) acc[mt][nt][c] = 0.f;

    uint4 pa0, pa1, pb0, pb1;
    pa0 = *(const uint4*)&Asrc_h[0];
    pa1 = *(const uint4*)&Asrc_l[0];
    pb0 = *(const uint4*)&Bsrc_h[0];
    pb1 = *(const uint4*)&Bsrc_l[0];
    *(uint4*)&S[0][0][0][sdst] = pa0;
    *(uint4*)&S[0][0][1][sdst] = pa1;
    *(uint4*)&S[0][1][0][sdst] = pb0;
    *(uint4*)&S[0][1][1][sdst] = pb1;
    __syncthreads();

    if (CH > 1) {
        pa0 = *(const uint4*)&Asrc_h[8];
        pa1 = *(const uint4*)&Asrc_l[8];
        pb0 = *(const uint4*)&Bsrc_h[8];
        pb1 = *(const uint4*)&Bsrc_l[8];
    }

    for (int kc = 0; kc < CH; kc++) {
        const int cur = kc & 1;
        if (kc < CH - 1) {
            *(uint4*)&S[cur ^ 1][0][0][sdst] = pa0;
            *(uint4*)&S[cur ^ 1][0][1][sdst] = pa1;
            *(uint4*)&S[cur ^ 1][1][0][sdst] = pb0;
            *(uint4*)&S[cur ^ 1][1][1][sdst] = pb1;
        }
        if (kc < CH - 2) {
            const int koff = (kc + 2) * 8;
            pa0 = *(const uint4*)&Asrc_h[koff];
            pa1 = *(const uint4*)&Asrc_l[koff];
            pb0 = *(const uint4*)&Bsrc_h[koff];
            pb1 = *(const uint4*)&Bsrc_l[koff];
        }

        const uint32_t* sAh = &S[cur][0][0][0];
        const uint32_t* sAl = &S[cur][0][1][0];
        const uint32_t* sBh = &S[cur][1][0][0];
        const uint32_t* sBl = &S[cur][1][1][0];

        uint32_t ah[4][4], al[4][4], bh[4][2], bl[4][2];
        #pragma unroll
        for (int mt = 0; mt < 4; mt++) {
            const int r0 = (warp_m * 64 + mt * 16 + g) * 12;
            const int r8 = r0 + 96;
            ah[mt][0] = sAh[r0 + tg];     ah[mt][1] = sAh[r8 + tg];
            ah[mt][2] = sAh[r0 + tg + 4]; ah[mt][3] = sAh[r8 + tg + 4];
            al[mt][0] = sAl[r0 + tg];     al[mt][1] = sAl[r8 + tg];
            al[mt][2] = sAl[r0 + tg + 4]; al[mt][3] = sAl[r8 + tg + 4];
        }
        #pragma unroll
        for (int nt = 0; nt < 4; nt++) {
            const int c0 = (warp_n * 32 + nt * 8 + g) * 12;
            bh[nt][0] = sBh[c0 + tg]; bh[nt][1] = sBh[c0 + tg + 4];
            bl[nt][0] = sBl[c0 + tg]; bl[nt][1] = sBl[c0 + tg + 4];
        }
        #pragma unroll
        for (int mt = 0; mt < 4; mt++)
            #pragma unroll
            for (int nt = 0; nt < 4; nt++) {
                mma16816(acc[mt][nt], ah[mt], bh[nt]);
                mma16816(acc[mt][nt], ah[mt], bl[nt]);
                mma16816(acc[mt][nt], al[mt], bh[nt]);
            }
        __syncthreads();
    }

    #pragma unroll
    for (int nt = 0; nt < 4; nt++) {
        const int col = n0 + warp_n * 32 + nt * 8 + 2 * tg;
        const float b0 = bias[col], b1 = bias[col + 1];
        float sc0, sc1, mu0, mu1, be0, be1;
        if (EPI == 2) {
            sc0 = bng[col] * rsqrtf(bnv[col] + 1e-5f);
            sc1 = bng[col + 1] * rsqrtf(bnv[col + 1] + 1e-5f);
            mu0 = bnm[col]; mu1 = bnm[col + 1];
            be0 = bnb[col]; be1 = bnb[col + 1];
        }
        #pragma unroll
        for (int mt = 0; mt < 4; mt++) {
            const size_t row = (size_t)m0 + warp_m * 64 + mt * 16 + g;
            float c0 = acc[mt][nt][0] + b0, c1 = acc[mt][nt][1] + b1;
            float c2 = acc[mt][nt][2] + b0, c3 = acc[mt][nt][3] + b1;
            if (EPI == 0) {
                *(float2*)&outf[row * LDC + col]       = make_float2(c0, c1);
                *(float2*)&outf[(row + 8) * LDC + col] = make_float2(c2, c3);
            } else if (EPI == 1) {
                float x0 = elu1(c0), x1 = elu1(c1), x2 = elu1(c2), x3 = elu1(c3);
                uint32_t hi, lo;
                split2(x0, x1, hi, lo);
                outh[row * KPO + (col >> 1)] = hi;
                outl[row * KPO + (col >> 1)] = lo;
                split2(x2, x3, hi, lo);
                outh[(row + 8) * KPO + (col >> 1)] = hi;
                outl[(row + 8) * KPO + (col >> 1)] = lo;
            } else {
                float v0 = (elu1(c0) - mu0) * sc0 + be0;
                float v1 = (elu1(c1) - mu1) * sc1 + be1;
                float v2 = (elu1(c2) - mu0) * sc0 + be0;
                float v3 = (elu1(c3) - mu1) * sc1 + be1;
                *(float2*)&outf[row * LDC + col]       = make_float2(v0, v1);
                *(float2*)&outf[(row + 8) * LDC + col] = make_float2(v2, v3);
            }
        }
    }
}

// ============================ Kernel D (pitch-132 wdw + float4 Xfs + L2 prefetch) ============================
constexpr int D_T = 256;
constexpr int D_WDW = 0;       // 8448 (64 x pitch132), [d*16+i][c]
constexpr int D_XF  = 8448;    // 4096 (16 x 256)
constexpr int D_SMEM = 12544;  // floats = 50176 B

__global__ void __launch_bounds__(D_T, 3)
kernelD(const float* __restrict__ fts, const float* __restrict__ wdw,
        const float* __restrict__ bdw)
{
    extern __shared__ float sm[];
    float* wdwT = sm + D_WDW;
    float* Xfs  = sm + D_XF;

    const int t = threadIdx.x;
    const int pbase = blockIdx.x * 16;
    const int warp = t >> 5, lane = t & 31;

    for (int i = t; i < 8192; i += D_T) {
        int c = i >> 6, r = i & 63;           // r = d*16 + k
        wdwT[r * 132 + c] = wdw[i];
    }
    for (int i = t; i < 4096; i += D_T)
        Xfs[i] = g_Xf[(size_t)pbase * 256 + i];
    __syncthreads();

    const int wh = warp & 1;                  // channel half
    const int c0 = (wh * 32 + lane) * 2;      // channel pair base (even)

    float4 bA = *(const float4*)&bdw[c0 * 4];
    float4 bB = *(const float4*)&bdw[(c0 + 1) * 4];

    // prefetch helper: each lane prefetches a distinct 128B line of the next
    // point's 16 fr rows (rows are 256B spans -> 32 lines per point per warp).
    const int pf_j = lane & 15, pf_half = (lane >> 4) * 32;

    #pragma unroll
    for (int p = 0; p < 4; p++) {
        const int g = p * 4 + (warp >> 1);
        const size_t pt = pbase + g;

        const float* src = (c0 < 64) ? (g_h2 + pt * 1024 + c0)
                                     : (fts  + pt * 1024 + (c0 - 64));
        float2 fr[16];
        #pragma unroll
        for (int j = 0; j < 16; j++)
            fr[j] = *(const float2*)&src[j * 64];

        // L2-prefetch next point's fr rows (issued before the compute phase)
        if (p < 3) {
            const size_t ptN = pt + 4;
            const float* baseN = (wh == 0) ? (g_h2 + ptN * 1024)
                                           : (fts  + ptN * 1024);
            l2pf(baseN + pf_j * 64 + pf_half);
        }

        float dA[4] = {bA.x, bA.y, bA.z, bA.w};
        float dB[4] = {bB.x, bB.y, bB.z, bB.w};

        #pragma unroll
        for (int i = 0; i < 16; i++) {
            const float* xr = &Xfs[g * 256 + i * 16];
            float4 x0 = *(const float4*)&xr[0];
            float4 x1 = *(const float4*)&xr[4];
            float4 x2 = *(const float4*)&xr[8];
            float4 x3 = *(const float4*)&xr[12];
            float fx0, fx1;
            fx0  = x0.x * fr[0].x  + x0.y * fr[1].x  + x0.z * fr[2].x  + x0.w * fr[3].x;
            fx0 += x1.x * fr[4].x  + x1.y * fr[5].x  + x1.z * fr[6].x  + x1.w * fr[7].x;
            fx0 += x2.x * fr[8].x  + x2.y * fr[9].x  + x2.z * fr[10].x + x2.w * fr[11].x;
            fx0 += x3.x * fr[12].x + x3.y * fr[13].x + x3.z * fr[14].x + x3.w * fr[15].x;
            fx1  = x0.x * fr[0].y  + x0.y * fr[1].y  + x0.z * fr[2].y  + x0.w * fr[3].y;
            fx1 += x1.x * fr[4].y  + x1.y * fr[5].y  + x1.z * fr[6].y  + x1.w * fr[7].y;
            fx1 += x2.x * fr[8].y  + x2.y * fr[9].y  + x2.z * fr[10].y + x2.w * fr[11].y;
            fx1 += x3.x * fr[12].y + x3.y * fr[13].y + x3.z * fr[14].y + x3.w * fr[15].y;

            #pragma unroll
            for (int d = 0; d < 4; d++) {
                float2 wd = *(const float2*)&wdwT[(d * 16 + i) * 132 + c0];
                dA[d] += fx0 * wd.x;
                dB[d] += fx1 * wd.y;
            }
        }

        uint32_t hi[4], lo[4];
        split2(dA[0], dA[1], hi[0], lo[0]);
        split2(dA[2], dA[3], hi[1], lo[1]);
        split2(dB[0], dB[1], hi[2], lo[2]);
        split2(dB[2], dB[3], hi[3], lo[3]);
        *(uint4*)&g_dwh[pt * 256 + c0 * 2] = make_uint4(hi[0], hi[1], hi[2], hi[3]);
        *(uint4*)&g_dwl[pt * 256 + c0 * 2] = make_uint4(lo[0], lo[1], lo[2], lo[3]);
    }
}

} // namespace

extern "C" void kernel_launch(void* const* d_in, const int* in_sizes, int n_in,
                              void* d_out, int out_size) {
    const float* rep_pt = (const float*)d_in[0];
    const float* pts    = (const float*)d_in[1];
    const float* fts    = (const float*)d_in[2];
    const float* w1     = (const float*)d_in[3];
    const float* b1     = (const float*)d_in[4];
    const float* w2     = (const float*)d_in[5];
    const float* b2     = (const float*)d_in[6];
    const float* wc1    = (const float*)d_in[7];
    const float* bc1    = (const float*)d_in[8];
    const float* wx1    = (const float*)d_in[9];
    const float* bx1    = (const float*)d_in[10];
    const float* wx2    = (const float*)d_in[11];
    const float* bx2    = (const float*)d_in[12];
    const float* wdw    = (const float*)d_in[13];
    const float* bdw    = (const float*)d_in[14];
    const float* wpw    = (const float*)d_in[15];
    const float* bpw    = (const float*)d_in[16];
    const float* bng    = (const float*)d_in[17];
    const float* bnb    = (const float*)d_in[18];
    const float* bnm    = (const float*)d_in[19];
    const float* bnv    = (const float*)d_in[20];
    float* out = (float*)d_out;

    static bool attr_done = false;
    if (!attr_done) {
        cudaFuncSetAttribute(kernelA, cudaFuncAttributeMaxDynamicSharedMemorySize,
                             A_SMEM * (int)sizeof(float));
        cudaFuncSetAttribute(kernelD, cudaFuncAttributeMaxDynamicSharedMemorySize,
                             D_SMEM * (int)sizeof(float));
        attr_done = true;
    }

    uint32_t *pX0h, *pX0l, *pX1h, *pX1l, *pdwh, *pdwl;
    uint32_t *pw1h, *pw1l, *pw2h, *pw2l, *pwph, *pwpl;
    float* pXf;
    cudaGetSymbolAddress((void**)&pX0h, g_X0h);
    cudaGetSymbolAddress((void**)&pX0l, g_X0l);
    cudaGetSymbolAddress((void**)&pX1h, g_X1h);
    cudaGetSymbolAddress((void**)&pX1l, g_X1l);
    cudaGetSymbolAddress((void**)&pXf,  g_Xf);
    cudaGetSymbolAddress((void**)&pdwh, g_dwh);
    cudaGetSymbolAddress((void**)&pdwl, g_dwl);
    cudaGetSymbolAddress((void**)&pw1h, g_wx1h);
    cudaGetSymbolAddress((void**)&pw1l, g_wx1l);
    cudaGetSymbolAddress((void**)&pw2h, g_wx2h);
    cudaGetSymbolAddress((void**)&pw2l, g_wx2l);
    cudaGetSymbolAddress((void**)&pwph, g_wpwh);
    cudaGetSymbolAddress((void**)&pwpl, g_wpwl);

    // A (with fused weight conversion): h2 (f32) + X0 (bf16 hi/lo)
    kernelA<<<NPTS / 64, A_T, A_SMEM * sizeof(float)>>>(
        rep_pt, pts, w1, b1, w2, b2, wc1, bc1, wx1, wx2, wpw);
    // B: X1 = elu(X0 @ wx1 + bx1) -> bf16 hi/lo
    bgemm<128, 2, 1><<<(NPTS / 128) * 2, 256>>>(
        pX0h, pX0l, pw1h, pw1l, bx1, nullptr, nullptr, nullptr, nullptr,
        nullptr, pX1h, pX1l);
    // C: Xf = X1 @ wx2 + bx2 -> f32
    bgemm<128, 2, 0><<<(NPTS / 128) * 2, 256>>>(
        pX1h, pX1l, pw2h, pw2l, bx2, nullptr, nullptr, nullptr, nullptr,
        pXf, nullptr, nullptr);
    // D: X-transform + depthwise -> dw bf16 hi/lo
    kernelD<<<NPTS / 16, D_T, D_SMEM * sizeof(float)>>>(fts, wdw, bdw);
    // E: out = BN(elu(dw @ wpw + bpw)) -> f32
    bgemm<256, 1, 2><<<NPTS / 128, 256>>>(
        pdwh, pdwl, pwph, pwpl, bpw, bng, bnb, bnm, bnv,
        out, nullptr, nullptr);
}

// round 13
// speedup vs baseline: 1.1271x; 1.0355x over previous
#include <cuda_runtime.h>
#include <cuda_bf16.h>
#include <math.h>
#include <stdint.h>

namespace {

constexpr int NPTS = 16384;

// ---------------- global scratch ----------------
__device__ float g_h2[NPTS * 1024];                       // [pt][k16][64] f32
__device__ __align__(16) uint32_t g_X0h[NPTS * 128];      // [pt][kp] bf16x2
__device__ __align__(16) uint32_t g_X0l[NPTS * 128];
__device__ __align__(16) uint32_t g_X1h[NPTS * 128];
__device__ __align__(16) uint32_t g_X1l[NPTS * 128];
__device__ float g_Xf[NPTS * 256];                        // f32 for kernelD
__device__ __align__(16) uint32_t g_dwh[NPTS * 256];      // [pt][kp of 512]
__device__ __align__(16) uint32_t g_dwl[NPTS * 256];
// converted weights, layout [n][kp]
__device__ __align__(16) uint32_t g_wx1h[256 * 128], g_wx1l[256 * 128];
__device__ __align__(16) uint32_t g_wx2h[256 * 128], g_wx2l[256 * 128];
__device__ __align__(16) uint32_t g_wpwh[128 * 256], g_wpwl[128 * 256];

__device__ __forceinline__ float elu1(float x) { return x > 0.f ? x : expm1f(x); }

__device__ __forceinline__ uint32_t packbf(float a, float b) {
    __nv_bfloat16 ha = __float2bfloat16_rn(a), hb = __float2bfloat16_rn(b);
    unsigned short ua = *reinterpret_cast<unsigned short*>(&ha);
    unsigned short ub = *reinterpret_cast<unsigned short*>(&hb);
    return (uint32_t)ua | ((uint32_t)ub << 16);
}
__device__ __forceinline__ void split2(float a, float b, uint32_t& hi, uint32_t& lo) {
    __nv_bfloat16 ha = __float2bfloat16_rn(a), hb = __float2bfloat16_rn(b);
    float ra = a - __bfloat162float(ha);
    float rb = b - __bfloat162float(hb);
    unsigned short ua = *reinterpret_cast<unsigned short*>(&ha);
    unsigned short ub = *reinterpret_cast<unsigned short*>(&hb);
    hi = (uint32_t)ua | ((uint32_t)ub << 16);
    lo = packbf(ra, rb);
}

// mma.sync m16n8k16 bf16 -> f32
__device__ __forceinline__ void mma16816(float* c, const uint32_t* a, const uint32_t* b) {
    asm("mma.sync.aligned.m16n8k16.row.col.f32.bf16.bf16.f32 "
        "{%0,%1,%2,%3}, {%4,%5,%6,%7}, {%8,%9}, {%0,%1,%2,%3};"
        : "+f"(c[0]), "+f"(c[1]), "+f"(c[2]), "+f"(c[3])
        : "r"(a[0]), "r"(a[1]), "r"(a[2]), "r"(a[3]), "r"(b[0]), "r"(b[1]));
}

__device__ __forceinline__ void l2pf(const float* p) {
    asm volatile("prefetch.global.L2 [%0];" :: "l"(p));
}

// ============================ Kernel A ============================
constexpr int A_T = 512;
constexpr int A_W1  = 0;
constexpr int A_B1  = 192;
constexpr int A_B2  = 256;
constexpr int A_PLT = 320;     // 768
constexpr int A_W2  = 1088;    // 4096
constexpr int A_WC1 = 5184;    // 12544 (256 x pitch49)
constexpr int A_H1  = 17728;   // 16896 (256 x pitch66)
constexpr int A_SMEM = 34624;

__global__ void __launch_bounds__(A_T, 1)
kernelA(const float* __restrict__ rep_pt, const float* __restrict__ pts,
        const float* __restrict__ w1,  const float* __restrict__ b1,
        const float* __restrict__ w2,  const float* __restrict__ b2,
        const float* __restrict__ wc1, const float* __restrict__ bc1,
        const float* __restrict__ wx1, const float* __restrict__ wx2,
        const float* __restrict__ wpw)
{
    extern __shared__ float sm[];
    float* w1s  = sm + A_W1;
    float* b1s  = sm + A_B1;
    float* b2s  = sm + A_B2;
    float* plT  = sm + A_PLT;
    float* w2s  = sm + A_W2;
    float* wc1s = sm + A_WC1;
    float* h1   = sm + A_H1;

    const int t = threadIdx.x;

    // ---- weight conversion slice (global->global, no barrier needed) ----
    if (t < 384) {
        int i = blockIdx.x * 384 + t;
        if (i < 32768) {
            int kp = i >> 8, n = i & 255;
            float v0 = wx1[(2 * kp) * 256 + n], v1 = wx1[(2 * kp + 1) * 256 + n];
            uint32_t hi, lo; split2(v0, v1, hi, lo);
            g_wx1h[n * 128 + kp] = hi; g_wx1l[n * 128 + kp] = lo;
        } else if (i < 65536) {
            int j = i - 32768; int kp = j >> 8, n = j & 255;
            float v0 = wx2[(2 * kp) * 256 + n], v1 = wx2[(2 * kp + 1) * 256 + n];
            uint32_t hi, lo; split2(v0, v1, hi, lo);
            g_wx2h[n * 128 + kp] = hi; g_wx2l[n * 128 + kp] = lo;
        } else {
            int j = i - 65536; int kp = j >> 7, n = j & 127;
            float v0 = wpw[(2 * kp) * 128 + n], v1 = wpw[(2 * kp + 1) * 128 + n];
            uint32_t hi, lo; split2(v0, v1, hi, lo);
            g_wpwh[n * 256 + kp] = hi; g_wpwl[n * 256 + kp] = lo;
        }
    }

    for (int i = t; i < 192; i += A_T) w1s[i] = w1[i];
    if (t < 64) { b1s[t] = b1[t]; b2s[t] = b2[t]; }
    for (int i = t; i < 4096; i += A_T) w2s[i] = w2[i];
    for (int i = t; i < 256 * 48; i += A_T) {
        int o = i / 48, m = i - o * 48;
        wc1s[o * 49 + m] = wc1[i];
    }

    for (int b = 0; b < 4; b++) {
        const int pbase = blockIdx.x * 64 + b * 16;
        __syncthreads();

        for (int i = t; i < 768; i += A_T) {
            int g = i / 48, r = i - g * 48, d = r >> 4, k = r & 15;
            int pp = pbase + g;
            plT[i] = pts[(pp * 16 + k) * 3 + d] - rep_pt[pp * 3 + d];
        }
        __syncthreads();

        {   // A1
            int row = t >> 1, g = row >> 4, k = row & 15, cb = (t & 1) * 32;
            float p0 = plT[g * 48 + k];
            float p1 = plT[g * 48 + 16 + k];
            float p2 = plT[g * 48 + 32 + k];
            #pragma unroll
            for (int c = 0; c < 32; c++) {
                float a = b1s[cb + c] + p0 * w1s[cb + c] + p1 * w1s[64 + cb + c]
                          + p2 * w1s[128 + cb + c];
                h1[row * 66 + cb + c] = elu1(a);
            }
        }
        __syncthreads();

        {   // A2: h2 -> g_h2
            int tc = t & 15, tr = t >> 4;
            float acc[8][4];
            #pragma unroll
            for (int i = 0; i < 8; i++)
                #pragma unroll
                for (int c = 0; c < 4; c++) acc[i][c] = b2s[tc * 4 + c];
            #pragma unroll 8
            for (int j = 0; j < 64; j++) {
                float4 w = *(const float4*)&w2s[j * 64 + tc * 4];
                #pragma unroll
                for (int i = 0; i < 8; i++) {
                    float hv = h1[(tr * 8 + i) * 66 + j];
                    acc[i][0] += hv * w.x; acc[i][1] += hv * w.y;
                    acc[i][2] += hv * w.z; acc[i][3] += hv * w.w;
                }
            }
            #pragma unroll
            for (int i = 0; i < 8; i++) {
                int r = tr * 8 + i;
                float4 o = {elu1(acc[i][0]), elu1(acc[i][1]),
                            elu1(acc[i][2]), elu1(acc[i][3])};
                *(float4*)&g_h2[(size_t)pbase * 1024 + r * 64 + tc * 4] = o;
            }
        }

        {   // B: X0 -> hi/lo
            int g = t >> 5, lane = t & 31;
            float acc[8];
            #pragma unroll
            for (int q = 0; q < 8; q++) acc[q] = bc1[lane + 32 * q];
            const float* pg = plT + g * 48;
            #pragma unroll 8
            for (int m = 0; m < 48; m++) {
                float pv = pg[m];
                #pragma unroll
                for (int q = 0; q < 8; q++) acc[q] += pv * wc1s[(lane + 32 * q) * 49 + m];
            }
            const size_t ptr = (size_t)(pbase + g) * 128;
            #pragma unroll
            for (int q = 0; q < 8; q++) {
                float x = elu1(acc[q]);
                float y = __shfl_xor_sync(0xffffffffu, x, 1);
                if ((lane & 1) == 0) {
                    uint32_t hi, lo; split2(x, y, hi, lo);
                    int kp = (lane + 32 * q) >> 1;
                    g_X0h[ptr + kp] = hi;
                    g_X0l[ptr + kp] = lo;
                }
            }
        }
    }
}

// ============================ bf16 tensor GEMM ============================
// Round-13: minblocks=2 (2 CTAs/SM) + term-outer mma order (acc reuse dist 16).
template <int KP, int NT, int EPI>
__global__ void __launch_bounds__(256, 2)
bgemm(const uint32_t* __restrict__ Ah, const uint32_t* __restrict__ Al,
      const uint32_t* __restrict__ Wh, const uint32_t* __restrict__ Wl,
      const float* __restrict__ bias,
      const float* __restrict__ bng, const float* __restrict__ bnb,
      const float* __restrict__ bnm, const float* __restrict__ bnv,
      float* __restrict__ outf, uint32_t* __restrict__ outh, uint32_t* __restrict__ outl)
{
    constexpr int CH = KP / 8;
    constexpr int LDC = NT * 128;
    constexpr int KPO = NT * 64;

    __shared__ __align__(16) uint32_t S[2][2][2][1536];

    const int t = threadIdx.x;
    const int wid = t >> 5, lane = t & 31;
    const int warp_m = wid & 1, warp_n = wid >> 1;
    const int g = lane >> 2, tg = lane & 3;
    const int bm = (int)blockIdx.x / NT, bn = (int)blockIdx.x % NT;
    const int m0 = bm * 128, n0 = bn * 128;

    const int srow = t >> 1;
    const int h4 = (t & 1) * 4;
    const uint32_t* Asrc_h = Ah + (size_t)(m0 + srow) * KP + h4;
    const uint32_t* Asrc_l = Al + (size_t)(m0 + srow) * KP + h4;
    const uint32_t* Bsrc_h = Wh + (size_t)(n0 + srow) * KP + h4;
    const uint32_t* Bsrc_l = Wl + (size_t)(n0 + srow) * KP + h4;
    const int sdst = srow * 12 + h4;

    float acc[4][4][4];
    #pragma unroll
    for (int mt = 0; mt < 4; mt++)
        #pragma unroll
        for (int nt = 0; nt < 4; nt++)
            #pragma unroll
            for (int c = 0; c < 4; c++) acc[mt][nt][c] = 0.f;

    uint4 pa0, pa1, pb0, pb1;
    pa0 = *(const uint4*)&Asrc_h[0];
    pa1 = *(const uint4*)&Asrc_l[0];
    pb0 = *(const uint4*)&Bsrc_h[0];
    pb1 = *(const uint4*)&Bsrc_l[0];
    *(uint4*)&S[0][0][0][sdst] = pa0;
    *(uint4*)&S[0][0][1][sdst] = pa1;
    *(uint4*)&S[0][1][0][sdst] = pb0;
    *(uint4*)&S[0][1][1][sdst] = pb1;
    __syncthreads();

    if (CH > 1) {
        pa0 = *(const uint4*)&Asrc_h[8];
        pa1 = *(const uint4*)&Asrc_l[8];
        pb0 = *(const uint4*)&Bsrc_h[8];
        pb1 = *(const uint4*)&Bsrc_l[8];
    }

    for (int kc = 0; kc < CH; kc++) {
        const int cur = kc & 1;
        if (kc < CH - 1) {
            *(uint4*)&S[cur ^ 1][0][0][sdst] = pa0;
            *(uint4*)&S[cur ^ 1][0][1][sdst] = pa1;
            *(uint4*)&S[cur ^ 1][1][0][sdst] = pb0;
            *(uint4*)&S[cur ^ 1][1][1][sdst] = pb1;
        }
        if (kc < CH - 2) {
            const int koff = (kc + 2) * 8;
            pa0 = *(const uint4*)&Asrc_h[koff];
            pa1 = *(const uint4*)&Asrc_l[koff];
            pb0 = *(const uint4*)&Bsrc_h[koff];
            pb1 = *(const uint4*)&Bsrc_l[koff];
        }

        const uint32_t* sAh = &S[cur][0][0][0];
        const uint32_t* sAl = &S[cur][0][1][0];
        const uint32_t* sBh = &S[cur][1][0][0];
        const uint32_t* sBl = &S[cur][1][1][0];

        uint32_t ah[4][4], al[4][4], bh[4][2], bl[4][2];
        #pragma unroll
        for (int mt = 0; mt < 4; mt++) {
            const int r0 = (warp_m * 64 + mt * 16 + g) * 12;
            const int r8 = r0 + 96;
            ah[mt][0] = sAh[r0 + tg];     ah[mt][1] = sAh[r8 + tg];
            ah[mt][2] = sAh[r0 + tg + 4]; ah[mt][3] = sAh[r8 + tg + 4];
            al[mt][0] = sAl[r0 + tg];     al[mt][1] = sAl[r8 + tg];
            al[mt][2] = sAl[r0 + tg + 4]; al[mt][3] = sAl[r8 + tg + 4];
        }
        #pragma unroll
        for (int nt = 0; nt < 4; nt++) {
            const int c0 = (warp_n * 32 + nt * 8 + g) * 12;
            bh[nt][0] = sBh[c0 + tg]; bh[nt][1] = sBh[c0 + tg + 4];
            bl[nt][0] = sBl[c0 + tg]; bl[nt][1] = sBl[c0 + tg + 4];
        }
        // term-outer: acc[mt][nt] reuse distance = 16 mma (was 1)
        #pragma unroll
        for (int term = 0; term < 3; term++)
            #pragma unroll
            for (int mt = 0; mt < 4; mt++)
                #pragma unroll
                for (int nt = 0; nt < 4; nt++)
                    mma16816(acc[mt][nt],
                             (term == 2) ? al[mt] : ah[mt],
                             (term == 1) ? bl[nt] : bh[nt]);
        __syncthreads();
    }

    #pragma unroll
    for (int nt = 0; nt < 4; nt++) {
        const int col = n0 + warp_n * 32 + nt * 8 + 2 * tg;
        const float b0 = bias[col], b1 = bias[col + 1];
        float sc0, sc1, mu0, mu1, be0, be1;
        if (EPI == 2) {
            sc0 = bng[col] * rsqrtf(bnv[col] + 1e-5f);
            sc1 = bng[col + 1] * rsqrtf(bnv[col + 1] + 1e-5f);
            mu0 = bnm[col]; mu1 = bnm[col + 1];
            be0 = bnb[col]; be1 = bnb[col + 1];
        }
        #pragma unroll
        for (int mt = 0; mt < 4; mt++) {
            const size_t row = (size_t)m0 + warp_m * 64 + mt * 16 + g;
            float c0 = acc[mt][nt][0] + b0, c1 = acc[mt][nt][1] + b1;
            float c2 = acc[mt][nt][2] + b0, c3 = acc[mt][nt][3] + b1;
            if (EPI == 0) {
                *(float2*)&outf[row * LDC + col]       = make_float2(c0, c1);
                *(float2*)&outf[(row + 8) * LDC + col] = make_float2(c2, c3);
            } else if (EPI == 1) {
                float x0 = elu1(c0), x1 = elu1(c1), x2 = elu1(c2), x3 = elu1(c3);
                uint32_t hi, lo;
                split2(x0, x1, hi, lo);
                outh[row * KPO + (col >> 1)] = hi;
                outl[row * KPO + (col >> 1)] = lo;
                split2(x2, x3, hi, lo);
                outh[(row + 8) * KPO + (col >> 1)] = hi;
                outl[(row + 8) * KPO + (col >> 1)] = lo;
            } else {
                float v0 = (elu1(c0) - mu0) * sc0 + be0;
                float v1 = (elu1(c1) - mu1) * sc1 + be1;
                float v2 = (elu1(c2) - mu0) * sc0 + be0;
                float v3 = (elu1(c3) - mu1) * sc1 + be1;
                *(float2*)&outf[row * LDC + col]       = make_float2(v0, v1);
                *(float2*)&outf[(row + 8) * LDC + col] = make_float2(v2, v3);
            }
        }
    }
}

// ============================ Kernel D (round-12 proven) ============================
constexpr int D_T = 256;
constexpr int D_WDW = 0;       // 8448 (64 x pitch132), [d*16+i][c]
constexpr int D_XF  = 8448;    // 4096 (16 x 256)
constexpr int D_SMEM = 12544;  // floats = 50176 B

__global__ void __launch_bounds__(D_T, 3)
kernelD(const float* __restrict__ fts, const float* __restrict__ wdw,
        const float* __restrict__ bdw)
{
    extern __shared__ float sm[];
    float* wdwT = sm + D_WDW;
    float* Xfs  = sm + D_XF;

    const int t = threadIdx.x;
    const int pbase = blockIdx.x * 16;
    const int warp = t >> 5, lane = t & 31;

    for (int i = t; i < 8192; i += D_T) {
        int c = i >> 6, r = i & 63;           // r = d*16 + k
        wdwT[r * 132 + c] = wdw[i];
    }
    for (int i = t; i < 4096; i += D_T)
        Xfs[i] = g_Xf[(size_t)pbase * 256 + i];
    __syncthreads();

    const int wh = warp & 1;                  // channel half
    const int c0 = (wh * 32 + lane) * 2;      // channel pair base (even)

    float4 bA = *(const float4*)&bdw[c0 * 4];
    float4 bB = *(const float4*)&bdw[(c0 + 1) * 4];

    const int pf_j = lane & 15, pf_half = (lane >> 4) * 32;

    #pragma unroll
    for (int p = 0; p < 4; p++) {
        const int g = p * 4 + (warp >> 1);
        const size_t pt = pbase + g;

        const float* src = (c0 < 64) ? (g_h2 + pt * 1024 + c0)
                                     : (fts  + pt * 1024 + (c0 - 64));
        float2 fr[16];
        #pragma unroll
        for (int j = 0; j < 16; j++)
            fr[j] = *(const float2*)&src[j * 64];

        if (p < 3) {
            const size_t ptN = pt + 4;
            const float* baseN = (wh == 0) ? (g_h2 + ptN * 1024)
                                           : (fts  + ptN * 1024);
            l2pf(baseN + pf_j * 64 + pf_half);
        }

        float dA[4] = {bA.x, bA.y, bA.z, bA.w};
        float dB[4] = {bB.x, bB.y, bB.z, bB.w};

        #pragma unroll
        for (int i = 0; i < 16; i++) {
            const float* xr = &Xfs[g * 256 + i * 16];
            float4 x0 = *(const float4*)&xr[0];
            float4 x1 = *(const float4*)&xr[4];
            float4 x2 = *(const float4*)&xr[8];
            float4 x3 = *(const float4*)&xr[12];
            float fx0, fx1;
            fx0  = x0.x * fr[0].x  + x0.y * fr[1].x  + x0.z * fr[2].x  + x0.w * fr[3].x;
            fx0 += x1.x * fr[4].x  + x1.y * fr[5].x  + x1.z * fr[6].x  + x1.w * fr[7].x;
            fx0 += x2.x * fr[8].x  + x2.y * fr[9].x  + x2.z * fr[10].x + x2.w * fr[11].x;
            fx0 += x3.x * fr[12].x + x3.y * fr[13].x + x3.z * fr[14].x + x3.w * fr[15].x;
            fx1  = x0.x * fr[0].y  + x0.y * fr[1].y  + x0.z * fr[2].y  + x0.w * fr[3].y;
            fx1 += x1.x * fr[4].y  + x1.y * fr[5].y  + x1.z * fr[6].y  + x1.w * fr[7].y;
            fx1 += x2.x * fr[8].y  + x2.y * fr[9].y  + x2.z * fr[10].y + x2.w * fr[11].y;
            fx1 += x3.x * fr[12].y + x3.y * fr[13].y + x3.z * fr[14].y + x3.w * fr[15].y;

            #pragma unroll
            for (int d = 0; d < 4; d++) {
                float2 wd = *(const float2*)&wdwT[(d * 16 + i) * 132 + c0];
                dA[d] += fx0 * wd.x;
                dB[d] += fx1 * wd.y;
            }
        }

        uint32_t hi[4], lo[4];
        split2(dA[0], dA[1], hi[0], lo[0]);
        split2(dA[2], dA[3], hi[1], lo[1]);
        split2(dB[0], dB[1], hi[2], lo[2]);
        split2(dB[2], dB[3], hi[3], lo[3]);
        *(uint4*)&g_dwh[pt * 256 + c0 * 2] = make_uint4(hi[0], hi[1], hi[2], hi[3]);
        *(uint4*)&g_dwl[pt * 256 + c0 * 2] = make_uint4(lo[0], lo[1], lo[2], lo[3]);
    }
}

} // namespace

extern "C" void kernel_launch(void* const* d_in, const int* in_sizes, int n_in,
                              void* d_out, int out_size) {
    const float* rep_pt = (const float*)d_in[0];
    const float* pts    = (const float*)d_in[1];
    const float* fts    = (const float*)d_in[2];
    const float* w1     = (const float*)d_in[3];
    const float* b1     = (const float*)d_in[4];
    const float* w2     = (const float*)d_in[5];
    const float* b2     = (const float*)d_in[6];
    const float* wc1    = (const float*)d_in[7];
    const float* bc1    = (const float*)d_in[8];
    const float* wx1    = (const float*)d_in[9];
    const float* bx1    = (const float*)d_in[10];
    const float* wx2    = (const float*)d_in[11];
    const float* bx2    = (const float*)d_in[12];
    const float* wdw    = (const float*)d_in[13];
    const float* bdw    = (const float*)d_in[14];
    const float* wpw    = (const float*)d_in[15];
    const float* bpw    = (const float*)d_in[16];
    const float* bng    = (const float*)d_in[17];
    const float* bnb    = (const float*)d_in[18];
    const float* bnm    = (const float*)d_in[19];
    const float* bnv    = (const float*)d_in[20];
    float* out = (float*)d_out;

    static bool attr_done = false;
    if (!attr_done) {
        cudaFuncSetAttribute(kernelA, cudaFuncAttributeMaxDynamicSharedMemorySize,
                             A_SMEM * (int)sizeof(float));
        cudaFuncSetAttribute(kernelD, cudaFuncAttributeMaxDynamicSharedMemorySize,
                             D_SMEM * (int)sizeof(float));
        attr_done = true;
    }

    uint32_t *pX0h, *pX0l, *pX1h, *pX1l, *pdwh, *pdwl;
    uint32_t *pw1h, *pw1l, *pw2h, *pw2l, *pwph, *pwpl;
    float* pXf;
    cudaGetSymbolAddress((void**)&pX0h, g_X0h);
    cudaGetSymbolAddress((void**)&pX0l, g_X0l);
    cudaGetSymbolAddress((void**)&pX1h, g_X1h);
    cudaGetSymbolAddress((void**)&pX1l, g_X1l);
    cudaGetSymbolAddress((void**)&pXf,  g_Xf);
    cudaGetSymbolAddress((void**)&pdwh, g_dwh);
    cudaGetSymbolAddress((void**)&pdwl, g_dwl);
    cudaGetSymbolAddress((void**)&pw1h, g_wx1h);
    cudaGetSymbolAddress((void**)&pw1l, g_wx1l);
    cudaGetSymbolAddress((void**)&pw2h, g_wx2h);
    cudaGetSymbolAddress((void**)&pw2l, g_wx2l);
    cudaGetSymbolAddress((void**)&pwph, g_wpwh);
    cudaGetSymbolAddress((void**)&pwpl, g_wpwl);

    // A (with fused weight conversion): h2 (f32) + X0 (bf16 hi/lo)
    kernelA<<<NPTS / 64, A_T, A_SMEM * sizeof(float)>>>(
        rep_pt, pts, w1, b1, w2, b2, wc1, bc1, wx1, wx2, wpw);
    // B: X1 = elu(X0 @ wx1 + bx1) -> bf16 hi/lo
    bgemm<128, 2, 1><<<(NPTS / 128) * 2, 256>>>(
        pX0h, pX0l, pw1h, pw1l, bx1, nullptr, nullptr, nullptr, nullptr,
        nullptr, pX1h, pX1l);
    // C: Xf = X1 @ wx2 + bx2 -> f32
    bgemm<128, 2, 0><<<(NPTS / 128) * 2, 256>>>(
        pX1h, pX1l, pw2h, pw2l, bx2, nullptr, nullptr, nullptr, nullptr,
        pXf, nullptr, nullptr);
    // D: X-transform + depthwise -> dw bf16 hi/lo
    kernelD<<<NPTS / 16, D_T, D_SMEM * sizeof(float)>>>(fts, wdw, bdw);
    // E: out = BN(elu(dw @ wpw + bpw)) -> f32
    bgemm<256, 1, 2><<<NPTS / 128, 256>>>(
        pdwh, pdwl, pwph, pwpl, bpw, bng, bnb, bnm, bnv,
        out, nullptr, nullptr);
}

// round 14
// speedup vs baseline: 1.2180x; 1.0807x over previous
#include <cuda_runtime.h>
#include <cuda_bf16.h>
#include <math.h>
#include <stdint.h>

namespace {

constexpr int NPTS = 16384;

// ---------------- global scratch ----------------
__device__ float g_h2[NPTS * 1024];                       // [pt][k16][64] f32
__device__ __align__(16) uint32_t g_X0h[NPTS * 128];      // [pt][kp] bf16x2
__device__ __align__(16) uint32_t g_X0l[NPTS * 128];
__device__ __align__(16) uint32_t g_X1h[NPTS * 128];
__device__ __align__(16) uint32_t g_X1l[NPTS * 128];
__device__ float g_Xf[NPTS * 256];                        // f32 for kernelD
__device__ __align__(16) uint32_t g_dwh[NPTS * 256];      // [pt][kp of 512]
__device__ __align__(16) uint32_t g_dwl[NPTS * 256];
// converted weights, layout [n][kp]
__device__ __align__(16) uint32_t g_wx1h[256 * 128], g_wx1l[256 * 128];
__device__ __align__(16) uint32_t g_wx2h[256 * 128], g_wx2l[256 * 128];
__device__ __align__(16) uint32_t g_wpwh[128 * 256], g_wpwl[128 * 256];

__device__ __forceinline__ float elu1(float x) { return x > 0.f ? x : expm1f(x); }

__device__ __forceinline__ uint32_t packbf(float a, float b) {
    __nv_bfloat16 ha = __float2bfloat16_rn(a), hb = __float2bfloat16_rn(b);
    unsigned short ua = *reinterpret_cast<unsigned short*>(&ha);
    unsigned short ub = *reinterpret_cast<unsigned short*>(&hb);
    return (uint32_t)ua | ((uint32_t)ub << 16);
}
__device__ __forceinline__ void split2(float a, float b, uint32_t& hi, uint32_t& lo) {
    __nv_bfloat16 ha = __float2bfloat16_rn(a), hb = __float2bfloat16_rn(b);
    float ra = a - __bfloat162float(ha);
    float rb = b - __bfloat162float(hb);
    unsigned short ua = *reinterpret_cast<unsigned short*>(&ha);
    unsigned short ub = *reinterpret_cast<unsigned short*>(&hb);
    hi = (uint32_t)ua | ((uint32_t)ub << 16);
    lo = packbf(ra, rb);
}

// mma.sync m16n8k16 bf16 -> f32
__device__ __forceinline__ void mma16816(float* c, const uint32_t* a, const uint32_t* b) {
    asm("mma.sync.aligned.m16n8k16.row.col.f32.bf16.bf16.f32 "
        "{%0,%1,%2,%3}, {%4,%5,%6,%7}, {%8,%9}, {%0,%1,%2,%3};"
        : "+f"(c[0]), "+f"(c[1]), "+f"(c[2]), "+f"(c[3])
        : "r"(a[0]), "r"(a[1]), "r"(a[2]), "r"(a[3]), "r"(b[0]), "r"(b[1]));
}

__device__ __forceinline__ void l2pf(const float* p) {
    asm volatile("prefetch.global.L2 [%0];" :: "l"(p));
}

// ============================ Kernel A ============================
// A1: h1 -> smem bf16 hi/lo (pitch 36). A2: h2 via mma.sync. B: X0 FFMA.
constexpr int A_T = 512;
constexpr int A_W1   = 0;       // 192
constexpr int A_B1   = 192;     // 64
constexpr int A_B2   = 256;     // 64
constexpr int A_PLT  = 320;     // 768
constexpr int A_WC1  = 1088;    // 12544 (256 x pitch49)
constexpr int A_H1H  = 13632;   // 9216 (256 x pitch36, uint32 as float slot)
constexpr int A_H1L  = 22848;   // 9216
constexpr int A_W2H  = 32064;   // 2304 (64 x pitch36)
constexpr int A_W2L  = 34368;   // 2304
constexpr int A_SMEM = 36672;   // floats = 146688 B

__global__ void __launch_bounds__(A_T, 1)
kernelA(const float* __restrict__ rep_pt, const float* __restrict__ pts,
        const float* __restrict__ w1,  const float* __restrict__ b1,
        const float* __restrict__ w2,  const float* __restrict__ b2,
        const float* __restrict__ wc1, const float* __restrict__ bc1,
        const float* __restrict__ wx1, const float* __restrict__ wx2,
        const float* __restrict__ wpw)
{
    extern __shared__ float sm[];
    float* w1s  = sm + A_W1;
    float* b1s  = sm + A_B1;
    float* b2s  = sm + A_B2;
    float* plT  = sm + A_PLT;
    float* wc1s = sm + A_WC1;
    uint32_t* h1h = (uint32_t*)(sm + A_H1H);
    uint32_t* h1l = (uint32_t*)(sm + A_H1L);
    uint32_t* w2h = (uint32_t*)(sm + A_W2H);
    uint32_t* w2l = (uint32_t*)(sm + A_W2L);

    const int t = threadIdx.x;

    // ---- weight conversion slice for B/C/E GEMMs (global->global) ----
    if (t < 384) {
        int i = blockIdx.x * 384 + t;
        if (i < 32768) {
            int kp = i >> 8, n = i & 255;
            float v0 = wx1[(2 * kp) * 256 + n], v1 = wx1[(2 * kp + 1) * 256 + n];
            uint32_t hi, lo; split2(v0, v1, hi, lo);
            g_wx1h[n * 128 + kp] = hi; g_wx1l[n * 128 + kp] = lo;
        } else if (i < 65536) {
            int j = i - 32768; int kp = j >> 8, n = j & 255;
            float v0 = wx2[(2 * kp) * 256 + n], v1 = wx2[(2 * kp + 1) * 256 + n];
            uint32_t hi, lo; split2(v0, v1, hi, lo);
            g_wx2h[n * 128 + kp] = hi; g_wx2l[n * 128 + kp] = lo;
        } else {
            int j = i - 65536; int kp = j >> 7, n = j & 127;
            float v0 = wpw[(2 * kp) * 128 + n], v1 = wpw[(2 * kp + 1) * 128 + n];
            uint32_t hi, lo; split2(v0, v1, hi, lo);
            g_wpwh[n * 256 + kp] = hi; g_wpwl[n * 256 + kp] = lo;
        }
    }

    for (int i = t; i < 192; i += A_T) w1s[i] = w1[i];
    if (t < 64) { b1s[t] = b1[t]; b2s[t] = b2[t]; }
    for (int i = t; i < 256 * 48; i += A_T) {
        int o = i / 48, m = i - o * 48;
        wc1s[o * 49 + m] = wc1[i];
    }
    // w2 -> smem hi/lo, layout [n=64][kp=32], pitch 36 (conflict-free fragments)
    for (int i = t; i < 2048; i += A_T) {
        int n = i >> 5, kp = i & 31;
        float v0 = w2[(2 * kp) * 64 + n], v1 = w2[(2 * kp + 1) * 64 + n];
        uint32_t hi, lo; split2(v0, v1, hi, lo);
        w2h[n * 36 + kp] = hi;
        w2l[n * 36 + kp] = lo;
    }

    const int wrp = t >> 5, lane = t & 31;
    const int fg = lane >> 2, ftg = lane & 3;

    for (int b = 0; b < 4; b++) {
        const int pbase = blockIdx.x * 64 + b * 16;
        __syncthreads();   // publishes weights (b=0) / retires h1 readers

        for (int i = t; i < 768; i += A_T) {
            int g = i / 48, r = i - g * 48, d = r >> 4, k = r & 15;
            int pp = pbase + g;
            plT[i] = pts[(pp * 16 + k) * 3 + d] - rep_pt[pp * 3 + d];
        }
        __syncthreads();

        {   // A1: h1 -> smem hi/lo (256 rows x 32 kp, pitch 36)
            int row = t >> 1, g = row >> 4, k = row & 15, cb = (t & 1) * 32;
            float p0 = plT[g * 48 + k];
            float p1 = plT[g * 48 + 16 + k];
            float p2 = plT[g * 48 + 32 + k];
            const int kp0 = cb >> 1;
            #pragma unroll
            for (int cc = 0; cc < 16; cc++) {
                int c = cb + 2 * cc;
                float a0 = b1s[c] + p0 * w1s[c] + p1 * w1s[64 + c] + p2 * w1s[128 + c];
                float a1 = b1s[c + 1] + p0 * w1s[c + 1] + p1 * w1s[64 + c + 1]
                           + p2 * w1s[128 + c + 1];
                a0 = elu1(a0); a1 = elu1(a1);
                uint32_t hi, lo; split2(a0, a1, hi, lo);
                h1h[row * 36 + kp0 + cc] = hi;
                h1l[row * 36 + kp0 + cc] = lo;
            }
        }
        __syncthreads();

        {   // A2: h2 = elu(h1 @ w2 + b2) via mma.sync; warp owns 16 rows
            float acc[8][4];
            #pragma unroll
            for (int nt = 0; nt < 8; nt++)
                #pragma unroll
                for (int c = 0; c < 4; c++) acc[nt][c] = 0.f;

            const int r0 = (wrp * 16 + fg) * 36;
            const int r8 = r0 + 8 * 36;

            #pragma unroll
            for (int ks = 0; ks < 4; ks++) {
                const int ko = ks * 8;
                uint32_t ah[4], al[4];
                ah[0] = h1h[r0 + ko + ftg];     ah[1] = h1h[r8 + ko + ftg];
                ah[2] = h1h[r0 + ko + ftg + 4]; ah[3] = h1h[r8 + ko + ftg + 4];
                al[0] = h1l[r0 + ko + ftg];     al[1] = h1l[r8 + ko + ftg];
                al[2] = h1l[r0 + ko + ftg + 4]; al[3] = h1l[r8 + ko + ftg + 4];
                uint32_t bh[8][2], bl[8][2];
                #pragma unroll
                for (int nt = 0; nt < 8; nt++) {
                    const int cb2 = (nt * 8 + fg) * 36 + ko;
                    bh[nt][0] = w2h[cb2 + ftg]; bh[nt][1] = w2h[cb2 + ftg + 4];
                    bl[nt][0] = w2l[cb2 + ftg]; bl[nt][1] = w2l[cb2 + ftg + 4];
                }
                #pragma unroll
                for (int term = 0; term < 3; term++)
                    #pragma unroll
                    for (int nt = 0; nt < 8; nt++)
                        mma16816(acc[nt],
                                 (term == 2) ? al : ah,
                                 (term == 1) ? bl[nt] : bh[nt]);
            }

            const int rowg = wrp * 16 + fg;
            float* dst = g_h2 + (size_t)pbase * 1024;
            #pragma unroll
            for (int nt = 0; nt < 8; nt++) {
                const int col = nt * 8 + 2 * ftg;
                float bb0 = b2s[col], bb1 = b2s[col + 1];
                *(float2*)&dst[rowg * 64 + col] =
                    make_float2(elu1(acc[nt][0] + bb0), elu1(acc[nt][1] + bb1));
                *(float2*)&dst[(rowg + 8) * 64 + col] =
                    make_float2(elu1(acc[nt][2] + bb0), elu1(acc[nt][3] + bb1));
            }
        }

        {   // B: X0 -> hi/lo
            int g = t >> 5, ln = t & 31;
            float acc[8];
            #pragma unroll
            for (int q = 0; q < 8; q++) acc[q] = bc1[ln + 32 * q];
            const float* pg = plT + g * 48;
            #pragma unroll 8
            for (int m = 0; m < 48; m++) {
                float pv = pg[m];
                #pragma unroll
                for (int q = 0; q < 8; q++) acc[q] += pv * wc1s[(ln + 32 * q) * 49 + m];
            }
            const size_t ptr = (size_t)(pbase + g) * 128;
            #pragma unroll
            for (int q = 0; q < 8; q++) {
                float x = elu1(acc[q]);
                float y = __shfl_xor_sync(0xffffffffu, x, 1);
                if ((ln & 1) == 0) {
                    uint32_t hi, lo; split2(x, y, hi, lo);
                    int kp = (ln + 32 * q) >> 1;
                    g_X0h[ptr + kp] = hi;
                    g_X0l[ptr + kp] = lo;
                }
            }
        }
    }
}

// ============================ bf16 tensor GEMM (round-13 proven) ============================
template <int KP, int NT, int EPI>
__global__ void __launch_bounds__(256, 2)
bgemm(const uint32_t* __restrict__ Ah, const uint32_t* __restrict__ Al,
      const uint32_t* __restrict__ Wh, const uint32_t* __restrict__ Wl,
      const float* __restrict__ bias,
      const float* __restrict__ bng, const float* __restrict__ bnb,
      const float* __restrict__ bnm, const float* __restrict__ bnv,
      float* __restrict__ outf, uint32_t* __restrict__ outh, uint32_t* __restrict__ outl)
{
    constexpr int CH = KP / 8;
    constexpr int LDC = NT * 128;
    constexpr int KPO = NT * 64;

    __shared__ __align__(16) uint32_t S[2][2][2][1536];

    const int t = threadIdx.x;
    const int wid = t >> 5, lane = t & 31;
    const int warp_m = wid & 1, warp_n = wid >> 1;
    const int g = lane >> 2, tg = lane & 3;
    const int bm = (int)blockIdx.x / NT, bn = (int)blockIdx.x % NT;
    const int m0 = bm * 128, n0 = bn * 128;

    const int srow = t >> 1;
    const int h4 = (t & 1) * 4;
    const uint32_t* Asrc_h = Ah + (size_t)(m0 + srow) * KP + h4;
    const uint32_t* Asrc_l = Al + (size_t)(m0 + srow) * KP + h4;
    const uint32_t* Bsrc_h = Wh + (size_t)(n0 + srow) * KP + h4;
    const uint32_t* Bsrc_l = Wl + (size_t)(n0 + srow) * KP + h4;
    const int sdst = srow * 12 + h4;

    float acc[4][4][4];
    #pragma unroll
    for (int mt = 0; mt < 4; mt++)
        #pragma unroll
        for (int nt = 0; nt < 4; nt++)
            #pragma unroll
            for (int c = 0; c < 4; c++) acc[mt][nt][c] = 0.f;

    uint4 pa0, pa1, pb0, pb1;
    pa0 = *(const uint4*)&Asrc_h[0];
    pa1 = *(const uint4*)&Asrc_l[0];
    pb0 = *(const uint4*)&Bsrc_h[0];
    pb1 = *(const uint4*)&Bsrc_l[0];
    *(uint4*)&S[0][0][0][sdst] = pa0;
    *(uint4*)&S[0][0][1][sdst] = pa1;
    *(uint4*)&S[0][1][0][sdst] = pb0;
    *(uint4*)&S[0][1][1][sdst] = pb1;
    __syncthreads();

    if (CH > 1) {
        pa0 = *(const uint4*)&Asrc_h[8];
        pa1 = *(const uint4*)&Asrc_l[8];
        pb0 = *(const uint4*)&Bsrc_h[8];
        pb1 = *(const uint4*)&Bsrc_l[8];
    }

    for (int kc = 0; kc < CH; kc++) {
        const int cur = kc & 1;
        if (kc < CH - 1) {
            *(uint4*)&S[cur ^ 1][0][0][sdst] = pa0;
            *(uint4*)&S[cur ^ 1][0][1][sdst] = pa1;
            *(uint4*)&S[cur ^ 1][1][0][sdst] = pb0;
            *(uint4*)&S[cur ^ 1][1][1][sdst] = pb1;
        }
        if (kc < CH - 2) {
            const int koff = (kc + 2) * 8;
            pa0 = *(const uint4*)&Asrc_h[koff];
            pa1 = *(const uint4*)&Asrc_l[koff];
            pb0 = *(const uint4*)&Bsrc_h[koff];
            pb1 = *(const uint4*)&Bsrc_l[koff];
        }

        const uint32_t* sAh = &S[cur][0][0][0];
        const uint32_t* sAl = &S[cur][0][1][0];
        const uint32_t* sBh = &S[cur][1][0][0];
        const uint32_t* sBl = &S[cur][1][1][0];

        uint32_t ah[4][4], al[4][4], bh[4][2], bl[4][2];
        #pragma unroll
        for (int mt = 0; mt < 4; mt++) {
            const int r0 = (warp_m * 64 + mt * 16 + g) * 12;
            const int r8 = r0 + 96;
            ah[mt][0] = sAh[r0 + tg];     ah[mt][1] = sAh[r8 + tg];
            ah[mt][2] = sAh[r0 + tg + 4]; ah[mt][3] = sAh[r8 + tg + 4];
            al[mt][0] = sAl[r0 + tg];     al[mt][1] = sAl[r8 + tg];
            al[mt][2] = sAl[r0 + tg + 4]; al[mt][3] = sAl[r8 + tg + 4];
        }
        #pragma unroll
        for (int nt = 0; nt < 4; nt++) {
            const int c0 = (warp_n * 32 + nt * 8 + g) * 12;
            bh[nt][0] = sBh[c0 + tg]; bh[nt][1] = sBh[c0 + tg + 4];
            bl[nt][0] = sBl[c0 + tg]; bl[nt][1] = sBl[c0 + tg + 4];
        }
        #pragma unroll
        for (int term = 0; term < 3; term++)
            #pragma unroll
            for (int mt = 0; mt < 4; mt++)
                #pragma unroll
                for (int nt = 0; nt < 4; nt++)
                    mma16816(acc[mt][nt],
                             (term == 2) ? al[mt] : ah[mt],
                             (term == 1) ? bl[nt] : bh[nt]);
        __syncthreads();
    }

    #pragma unroll
    for (int nt = 0; nt < 4; nt++) {
        const int col = n0 + warp_n * 32 + nt * 8 + 2 * tg;
        const float b0 = bias[col], b1 = bias[col + 1];
        float sc0, sc1, mu0, mu1, be0, be1;
        if (EPI == 2) {
            sc0 = bng[col] * rsqrtf(bnv[col] + 1e-5f);
            sc1 = bng[col + 1] * rsqrtf(bnv[col + 1] + 1e-5f);
            mu0 = bnm[col]; mu1 = bnm[col + 1];
            be0 = bnb[col]; be1 = bnb[col + 1];
        }
        #pragma unroll
        for (int mt = 0; mt < 4; mt++) {
            const size_t row = (size_t)m0 + warp_m * 64 + mt * 16 + g;
            float c0 = acc[mt][nt][0] + b0, c1 = acc[mt][nt][1] + b1;
            float c2 = acc[mt][nt][2] + b0, c3 = acc[mt][nt][3] + b1;
            if (EPI == 0) {
                *(float2*)&outf[row * LDC + col]       = make_float2(c0, c1);
                *(float2*)&outf[(row + 8) * LDC + col] = make_float2(c2, c3);
            } else if (EPI == 1) {
                float x0 = elu1(c0), x1 = elu1(c1), x2 = elu1(c2), x3 = elu1(c3);
                uint32_t hi, lo;
                split2(x0, x1, hi, lo);
                outh[row * KPO + (col >> 1)] = hi;
                outl[row * KPO + (col >> 1)] = lo;
                split2(x2, x3, hi, lo);
                outh[(row + 8) * KPO + (col >> 1)] = hi;
                outl[(row + 8) * KPO + (col >> 1)] = lo;
            } else {
                float v0 = (elu1(c0) - mu0) * sc0 + be0;
                float v1 = (elu1(c1) - mu1) * sc1 + be1;
                float v2 = (elu1(c2) - mu0) * sc0 + be0;
                float v3 = (elu1(c3) - mu1) * sc1 + be1;
                *(float2*)&outf[row * LDC + col]       = make_float2(v0, v1);
                *(float2*)&outf[(row + 8) * LDC + col] = make_float2(v2, v3);
            }
        }
    }
}

// ============================ Kernel D (round-12/13 proven) ============================
constexpr int D_T = 256;
constexpr int D_WDW = 0;       // 8448 (64 x pitch132), [d*16+i][c]
constexpr int D_XF  = 8448;    // 4096 (16 x 256)
constexpr int D_SMEM = 12544;  // floats = 50176 B

__global__ void __launch_bounds__(D_T, 3)
kernelD(const float* __restrict__ fts, const float* __restrict__ wdw,
        const float* __restrict__ bdw)
{
    extern __shared__ float sm[];
    float* wdwT = sm + D_WDW;
    float* Xfs  = sm + D_XF;

    const int t = threadIdx.x;
    const int pbase = blockIdx.x * 16;
    const int warp = t >> 5, lane = t & 31;

    for (int i = t; i < 8192; i += D_T) {
        int c = i >> 6, r = i & 63;           // r = d*16 + k
        wdwT[r * 132 + c] = wdw[i];
    }
    for (int i = t; i < 4096; i += D_T)
        Xfs[i] = g_Xf[(size_t)pbase * 256 + i];
    __syncthreads();

    const int wh = warp & 1;
    const int c0 = (wh * 32 + lane) * 2;

    float4 bA = *(const float4*)&bdw[c0 * 4];
    float4 bB = *(const float4*)&bdw[(c0 + 1) * 4];

    const int pf_j = lane & 15, pf_half = (lane >> 4) * 32;

    #pragma unroll
    for (int p = 0; p < 4; p++) {
        const int g = p * 4 + (warp >> 1);
        const size_t pt = pbase + g;

        const float* src = (c0 < 64) ? (g_h2 + pt * 1024 + c0)
                                     : (fts  + pt * 1024 + (c0 - 64));
        float2 fr[16];
        #pragma unroll
        for (int j = 0; j < 16; j++)
            fr[j] = *(const float2*)&src[j * 64];

        if (p < 3) {
            const size_t ptN = pt + 4;
            const float* baseN = (wh == 0) ? (g_h2 + ptN * 1024)
                                           : (fts  + ptN * 1024);
            l2pf(baseN + pf_j * 64 + pf_half);
        }

        float dA[4] = {bA.x, bA.y, bA.z, bA.w};
        float dB[4] = {bB.x, bB.y, bB.z, bB.w};

        #pragma unroll
        for (int i = 0; i < 16; i++) {
            const float* xr = &Xfs[g * 256 + i * 16];
            float4 x0 = *(const float4*)&xr[0];
            float4 x1 = *(const float4*)&xr[4];
            float4 x2 = *(const float4*)&xr[8];
            float4 x3 = *(const float4*)&xr[12];
            float fx0, fx1;
            fx0  = x0.x * fr[0].x  + x0.y * fr[1].x  + x0.z * fr[2].x  + x0.w * fr[3].x;
            fx0 += x1.x * fr[4].x  + x1.y * fr[5].x  + x1.z * fr[6].x  + x1.w * fr[7].x;
            fx0 += x2.x * fr[8].x  + x2.y * fr[9].x  + x2.z * fr[10].x + x2.w * fr[11].x;
            fx0 += x3.x * fr[12].x + x3.y * fr[13].x + x3.z * fr[14].x + x3.w * fr[15].x;
            fx1  = x0.x * fr[0].y  + x0.y * fr[1].y  + x0.z * fr[2].y  + x0.w * fr[3].y;
            fx1 += x1.x * fr[4].y  + x1.y * fr[5].y  + x1.z * fr[6].y  + x1.w * fr[7].y;
            fx1 += x2.x * fr[8].y  + x2.y * fr[9].y  + x2.z * fr[10].y + x2.w * fr[11].y;
            fx1 += x3.x * fr[12].y + x3.y * fr[13].y + x3.z * fr[14].y + x3.w * fr[15].y;

            #pragma unroll
            for (int d = 0; d < 4; d++) {
                float2 wd = *(const float2*)&wdwT[(d * 16 + i) * 132 + c0];
                dA[d] += fx0 * wd.x;
                dB[d] += fx1 * wd.y;
            }
        }

        uint32_t hi[4], lo[4];
        split2(dA[0], dA[1], hi[0], lo[0]);
        split2(dA[2], dA[3], hi[1], lo[1]);
        split2(dB[0], dB[1], hi[2], lo[2]);
        split2(dB[2], dB[3], hi[3], lo[3]);
        *(uint4*)&g_dwh[pt * 256 + c0 * 2] = make_uint4(hi[0], hi[1], hi[2], hi[3]);
        *(uint4*)&g_dwl[pt * 256 + c0 * 2] = make_uint4(lo[0], lo[1], lo[2], lo[3]);
    }
}

} // namespace

extern "C" void kernel_launch(void* const* d_in, const int* in_sizes, int n_in,
                              void* d_out, int out_size) {
    const float* rep_pt = (const float*)d_in[0];
    const float* pts    = (const float*)d_in[1];
    const float* fts    = (const float*)d_in[2];
    const float* w1     = (const float*)d_in[3];
    const float* b1     = (const float*)d_in[4];
    const float* w2     = (const float*)d_in[5];
    const float* b2     = (const float*)d_in[6];
    const float* wc1    = (const float*)d_in[7];
    const float* bc1    = (const float*)d_in[8];
    const float* wx1    = (const float*)d_in[9];
    const float* bx1    = (const float*)d_in[10];
    const float* wx2    = (const float*)d_in[11];
    const float* bx2    = (const float*)d_in[12];
    const float* wdw    = (const float*)d_in[13];
    const float* bdw    = (const float*)d_in[14];
    const float* wpw    = (const float*)d_in[15];
    const float* bpw    = (const float*)d_in[16];
    const float* bng    = (const float*)d_in[17];
    const float* bnb    = (const float*)d_in[18];
    const float* bnm    = (const float*)d_in[19];
    const float* bnv    = (const float*)d_in[20];
    float* out = (float*)d_out;

    static bool attr_done = false;
    if (!attr_done) {
        cudaFuncSetAttribute(kernelA, cudaFuncAttributeMaxDynamicSharedMemorySize,
                             A_SMEM * (int)sizeof(float));
        cudaFuncSetAttribute(kernelD, cudaFuncAttributeMaxDynamicSharedMemorySize,
                             D_SMEM * (int)sizeof(float));
        attr_done = true;
    }

    uint32_t *pX0h, *pX0l, *pX1h, *pX1l, *pdwh, *pdwl;
    uint32_t *pw1h, *pw1l, *pw2h, *pw2l, *pwph, *pwpl;
    float* pXf;
    cudaGetSymbolAddress((void**)&pX0h, g_X0h);
    cudaGetSymbolAddress((void**)&pX0l, g_X0l);
    cudaGetSymbolAddress((void**)&pX1h, g_X1h);
    cudaGetSymbolAddress((void**)&pX1l, g_X1l);
    cudaGetSymbolAddress((void**)&pXf,  g_Xf);
    cudaGetSymbolAddress((void**)&pdwh, g_dwh);
    cudaGetSymbolAddress((void**)&pdwl, g_dwl);
    cudaGetSymbolAddress((void**)&pw1h, g_wx1h);
    cudaGetSymbolAddress((void**)&pw1l, g_wx1l);
    cudaGetSymbolAddress((void**)&pw2h, g_wx2h);
    cudaGetSymbolAddress((void**)&pw2l, g_wx2l);
    cudaGetSymbolAddress((void**)&pwph, g_wpwh);
    cudaGetSymbolAddress((void**)&pwpl, g_wpwl);

    // A: h1 -> h2 (mma) + X0 (hi/lo), with fused weight conversion
    kernelA<<<NPTS / 64, A_T, A_SMEM * sizeof(float)>>>(
        rep_pt, pts, w1, b1, w2, b2, wc1, bc1, wx1, wx2, wpw);
    // B: X1 = elu(X0 @ wx1 + bx1) -> bf16 hi/lo
    bgemm<128, 2, 1><<<(NPTS / 128) * 2, 256>>>(
        pX0h, pX0l, pw1h, pw1l, bx1, nullptr, nullptr, nullptr, nullptr,
        nullptr, pX1h, pX1l);
    // C: Xf = X1 @ wx2 + bx2 -> f32
    bgemm<128, 2, 0><<<(NPTS / 128) * 2, 256>>>(
        pX1h, pX1l, pw2h, pw2l, bx2, nullptr, nullptr, nullptr, nullptr,
        pXf, nullptr, nullptr);
    // D: X-transform + depthwise -> dw bf16 hi/lo
    kernelD<<<NPTS / 16, D_T, D_SMEM * sizeof(float)>>>(fts, wdw, bdw);
    // E: out = BN(elu(dw @ wpw + bpw)) -> f32
    bgemm<256, 1, 2><<<NPTS / 128, 256>>>(
        pdwh, pdwl, pwph, pwpl, bpw, bng, bnb, bnm, bnv,
        out, nullptr, nullptr);
}

// round 15
// speedup vs baseline: 1.2757x; 1.0474x over previous
#include <cuda_runtime.h>
#include <cuda_bf16.h>
#include <math.h>
#include <stdint.h>

namespace {

constexpr int NPTS = 16384;

// ---------------- global scratch ----------------
__device__ float g_h2[NPTS * 1024];                       // [pt][k16][64] f32
__device__ __align__(16) uint32_t g_X0h[NPTS * 128];      // [pt][kp] bf16x2
__device__ __align__(16) uint32_t g_X0l[NPTS * 128];
__device__ __align__(16) uint32_t g_X1h[NPTS * 128];
__device__ __align__(16) uint32_t g_X1l[NPTS * 128];
__device__ float g_Xf[NPTS * 256];                        // f32 for kernelD
__device__ __align__(16) uint32_t g_dwh[NPTS * 256];      // [pt][kp of 512]
__device__ __align__(16) uint32_t g_dwl[NPTS * 256];
// converted weights, layout [n][kp]
__device__ __align__(16) uint32_t g_wx1h[256 * 128], g_wx1l[256 * 128];
__device__ __align__(16) uint32_t g_wx2h[256 * 128], g_wx2l[256 * 128];
__device__ __align__(16) uint32_t g_wpwh[128 * 256], g_wpwl[128 * 256];

__device__ __forceinline__ float elu1(float x) { return x > 0.f ? x : expm1f(x); }

__device__ __forceinline__ uint32_t packbf(float a, float b) {
    __nv_bfloat16 ha = __float2bfloat16_rn(a), hb = __float2bfloat16_rn(b);
    unsigned short ua = *reinterpret_cast<unsigned short*>(&ha);
    unsigned short ub = *reinterpret_cast<unsigned short*>(&hb);
    return (uint32_t)ua | ((uint32_t)ub << 16);
}
__device__ __forceinline__ void split2(float a, float b, uint32_t& hi, uint32_t& lo) {
    __nv_bfloat16 ha = __float2bfloat16_rn(a), hb = __float2bfloat16_rn(b);
    float ra = a - __bfloat162float(ha);
    float rb = b - __bfloat162float(hb);
    unsigned short ua = *reinterpret_cast<unsigned short*>(&ha);
    unsigned short ub = *reinterpret_cast<unsigned short*>(&hb);
    hi = (uint32_t)ua | ((uint32_t)ub << 16);
    lo = packbf(ra, rb);
}

// mma.sync m16n8k16 bf16 -> f32
__device__ __forceinline__ void mma16816(float* c, const uint32_t* a, const uint32_t* b) {
    asm("mma.sync.aligned.m16n8k16.row.col.f32.bf16.bf16.f32 "
        "{%0,%1,%2,%3}, {%4,%5,%6,%7}, {%8,%9}, {%0,%1,%2,%3};"
        : "+f"(c[0]), "+f"(c[1]), "+f"(c[2]), "+f"(c[3])
        : "r"(a[0]), "r"(a[1]), "r"(a[2]), "r"(a[3]), "r"(b[0]), "r"(b[1]));
}

__device__ __forceinline__ void l2pf(const float* p) {
    asm volatile("prefetch.global.L2 [%0];" :: "l"(p));
}

// ============================ Kernel A (round-14 proven) ============================
constexpr int A_T = 512;
constexpr int A_W1   = 0;       // 192
constexpr int A_B1   = 192;     // 64
constexpr int A_B2   = 256;     // 64
constexpr int A_PLT  = 320;     // 768
constexpr int A_WC1  = 1088;    // 12544 (256 x pitch49)
constexpr int A_H1H  = 13632;   // 9216 (256 x pitch36)
constexpr int A_H1L  = 22848;   // 9216
constexpr int A_W2H  = 32064;   // 2304 (64 x pitch36)
constexpr int A_W2L  = 34368;   // 2304
constexpr int A_SMEM = 36672;   // floats = 146688 B

__global__ void __launch_bounds__(A_T, 1)
kernelA(const float* __restrict__ rep_pt, const float* __restrict__ pts,
        const float* __restrict__ w1,  const float* __restrict__ b1,
        const float* __restrict__ w2,  const float* __restrict__ b2,
        const float* __restrict__ wc1, const float* __restrict__ bc1,
        const float* __restrict__ wx1, const float* __restrict__ wx2,
        const float* __restrict__ wpw)
{
    extern __shared__ float sm[];
    float* w1s  = sm + A_W1;
    float* b1s  = sm + A_B1;
    float* b2s  = sm + A_B2;
    float* plT  = sm + A_PLT;
    float* wc1s = sm + A_WC1;
    uint32_t* h1h = (uint32_t*)(sm + A_H1H);
    uint32_t* h1l = (uint32_t*)(sm + A_H1L);
    uint32_t* w2h = (uint32_t*)(sm + A_W2H);
    uint32_t* w2l = (uint32_t*)(sm + A_W2L);

    const int t = threadIdx.x;

    // ---- weight conversion slice for B/C/E GEMMs ----
    if (t < 384) {
        int i = blockIdx.x * 384 + t;
        if (i < 32768) {
            int kp = i >> 8, n = i & 255;
            float v0 = wx1[(2 * kp) * 256 + n], v1 = wx1[(2 * kp + 1) * 256 + n];
            uint32_t hi, lo; split2(v0, v1, hi, lo);
            g_wx1h[n * 128 + kp] = hi; g_wx1l[n * 128 + kp] = lo;
        } else if (i < 65536) {
            int j = i - 32768; int kp = j >> 8, n = j & 255;
            float v0 = wx2[(2 * kp) * 256 + n], v1 = wx2[(2 * kp + 1) * 256 + n];
            uint32_t hi, lo; split2(v0, v1, hi, lo);
            g_wx2h[n * 128 + kp] = hi; g_wx2l[n * 128 + kp] = lo;
        } else {
            int j = i - 65536; int kp = j >> 7, n = j & 127;
            float v0 = wpw[(2 * kp) * 128 + n], v1 = wpw[(2 * kp + 1) * 128 + n];
            uint32_t hi, lo; split2(v0, v1, hi, lo);
            g_wpwh[n * 256 + kp] = hi; g_wpwl[n * 256 + kp] = lo;
        }
    }

    for (int i = t; i < 192; i += A_T) w1s[i] = w1[i];
    if (t < 64) { b1s[t] = b1[t]; b2s[t] = b2[t]; }
    for (int i = t; i < 256 * 48; i += A_T) {
        int o = i / 48, m = i - o * 48;
        wc1s[o * 49 + m] = wc1[i];
    }
    for (int i = t; i < 2048; i += A_T) {
        int n = i >> 5, kp = i & 31;
        float v0 = w2[(2 * kp) * 64 + n], v1 = w2[(2 * kp + 1) * 64 + n];
        uint32_t hi, lo; split2(v0, v1, hi, lo);
        w2h[n * 36 + kp] = hi;
        w2l[n * 36 + kp] = lo;
    }

    const int wrp = t >> 5, lane = t & 31;
    const int fg = lane >> 2, ftg = lane & 3;

    for (int b = 0; b < 4; b++) {
        const int pbase = blockIdx.x * 64 + b * 16;
        __syncthreads();

        for (int i = t; i < 768; i += A_T) {
            int g = i / 48, r = i - g * 48, d = r >> 4, k = r & 15;
            int pp = pbase + g;
            plT[i] = pts[(pp * 16 + k) * 3 + d] - rep_pt[pp * 3 + d];
        }
        __syncthreads();

        {   // A1: h1 -> smem hi/lo (256 rows x 32 kp, pitch 36)
            int row = t >> 1, g = row >> 4, k = row & 15, cb = (t & 1) * 32;
            float p0 = plT[g * 48 + k];
            float p1 = plT[g * 48 + 16 + k];
            float p2 = plT[g * 48 + 32 + k];
            const int kp0 = cb >> 1;
            #pragma unroll
            for (int cc = 0; cc < 16; cc++) {
                int c = cb + 2 * cc;
                float a0 = b1s[c] + p0 * w1s[c] + p1 * w1s[64 + c] + p2 * w1s[128 + c];
                float a1 = b1s[c + 1] + p0 * w1s[c + 1] + p1 * w1s[64 + c + 1]
                           + p2 * w1s[128 + c + 1];
                a0 = elu1(a0); a1 = elu1(a1);
                uint32_t hi, lo; split2(a0, a1, hi, lo);
                h1h[row * 36 + kp0 + cc] = hi;
                h1l[row * 36 + kp0 + cc] = lo;
            }
        }
        __syncthreads();

        {   // A2: h2 = elu(h1 @ w2 + b2) via mma.sync
            float acc[8][4];
            #pragma unroll
            for (int nt = 0; nt < 8; nt++)
                #pragma unroll
                for (int c = 0; c < 4; c++) acc[nt][c] = 0.f;

            const int r0 = (wrp * 16 + fg) * 36;
            const int r8 = r0 + 8 * 36;

            #pragma unroll
            for (int ks = 0; ks < 4; ks++) {
                const int ko = ks * 8;
                uint32_t ah[4], al[4];
                ah[0] = h1h[r0 + ko + ftg];     ah[1] = h1h[r8 + ko + ftg];
                ah[2] = h1h[r0 + ko + ftg + 4]; ah[3] = h1h[r8 + ko + ftg + 4];
                al[0] = h1l[r0 + ko + ftg];     al[1] = h1l[r8 + ko + ftg];
                al[2] = h1l[r0 + ko + ftg + 4]; al[3] = h1l[r8 + ko + ftg + 4];
                uint32_t bh[8][2], bl[8][2];
                #pragma unroll
                for (int nt = 0; nt < 8; nt++) {
                    const int cb2 = (nt * 8 + fg) * 36 + ko;
                    bh[nt][0] = w2h[cb2 + ftg]; bh[nt][1] = w2h[cb2 + ftg + 4];
                    bl[nt][0] = w2l[cb2 + ftg]; bl[nt][1] = w2l[cb2 + ftg + 4];
                }
                #pragma unroll
                for (int term = 0; term < 3; term++)
                    #pragma unroll
                    for (int nt = 0; nt < 8; nt++)
                        mma16816(acc[nt],
                                 (term == 2) ? al : ah,
                                 (term == 1) ? bl[nt] : bh[nt]);
            }

            const int rowg = wrp * 16 + fg;
            float* dst = g_h2 + (size_t)pbase * 1024;
            #pragma unroll
            for (int nt = 0; nt < 8; nt++) {
                const int col = nt * 8 + 2 * ftg;
                float bb0 = b2s[col], bb1 = b2s[col + 1];
                *(float2*)&dst[rowg * 64 + col] =
                    make_float2(elu1(acc[nt][0] + bb0), elu1(acc[nt][1] + bb1));
                *(float2*)&dst[(rowg + 8) * 64 + col] =
                    make_float2(elu1(acc[nt][2] + bb0), elu1(acc[nt][3] + bb1));
            }
        }

        {   // B: X0 -> hi/lo
            int g = t >> 5, ln = t & 31;
            float acc[8];
            #pragma unroll
            for (int q = 0; q < 8; q++) acc[q] = bc1[ln + 32 * q];
            const float* pg = plT + g * 48;
            #pragma unroll 8
            for (int m = 0; m < 48; m++) {
                float pv = pg[m];
                #pragma unroll
                for (int q = 0; q < 8; q++) acc[q] += pv * wc1s[(ln + 32 * q) * 49 + m];
            }
            const size_t ptr = (size_t)(pbase + g) * 128;
            #pragma unroll
            for (int q = 0; q < 8; q++) {
                float x = elu1(acc[q]);
                float y = __shfl_xor_sync(0xffffffffu, x, 1);
                if ((ln & 1) == 0) {
                    uint32_t hi, lo; split2(x, y, hi, lo);
                    int kp = (ln + 32 * q) >> 1;
                    g_X0h[ptr + kp] = hi;
                    g_X0l[ptr + kp] = lo;
                }
            }
        }
    }
}

// ============================ bf16 tensor GEMM (round-13 proven) ============================
template <int KP, int NT, int EPI>
__global__ void __launch_bounds__(256, 2)
bgemm(const uint32_t* __restrict__ Ah, const uint32_t* __restrict__ Al,
      const uint32_t* __restrict__ Wh, const uint32_t* __restrict__ Wl,
      const float* __restrict__ bias,
      const float* __restrict__ bng, const float* __restrict__ bnb,
      const float* __restrict__ bnm, const float* __restrict__ bnv,
      float* __restrict__ outf, uint32_t* __restrict__ outh, uint32_t* __restrict__ outl)
{
    constexpr int CH = KP / 8;
    constexpr int LDC = NT * 128;
    constexpr int KPO = NT * 64;

    __shared__ __align__(16) uint32_t S[2][2][2][1536];

    const int t = threadIdx.x;
    const int wid = t >> 5, lane = t & 31;
    const int warp_m = wid & 1, warp_n = wid >> 1;
    const int g = lane >> 2, tg = lane & 3;
    const int bm = (int)blockIdx.x / NT, bn = (int)blockIdx.x % NT;
    const int m0 = bm * 128, n0 = bn * 128;

    const int srow = t >> 1;
    const int h4 = (t & 1) * 4;
    const uint32_t* Asrc_h = Ah + (size_t)(m0 + srow) * KP + h4;
    const uint32_t* Asrc_l = Al + (size_t)(m0 + srow) * KP + h4;
    const uint32_t* Bsrc_h = Wh + (size_t)(n0 + srow) * KP + h4;
    const uint32_t* Bsrc_l = Wl + (size_t)(n0 + srow) * KP + h4;
    const int sdst = srow * 12 + h4;

    float acc[4][4][4];
    #pragma unroll
    for (int mt = 0; mt < 4; mt++)
        #pragma unroll
        for (int nt = 0; nt < 4; nt++)
            #pragma unroll
            for (int c = 0; c < 4; c++) acc[mt][nt][c] = 0.f;

    uint4 pa0, pa1, pb0, pb1;
    pa0 = *(const uint4*)&Asrc_h[0];
    pa1 = *(const uint4*)&Asrc_l[0];
    pb0 = *(const uint4*)&Bsrc_h[0];
    pb1 = *(const uint4*)&Bsrc_l[0];
    *(uint4*)&S[0][0][0][sdst] = pa0;
    *(uint4*)&S[0][0][1][sdst] = pa1;
    *(uint4*)&S[0][1][0][sdst] = pb0;
    *(uint4*)&S[0][1][1][sdst] = pb1;
    __syncthreads();

    if (CH > 1) {
        pa0 = *(const uint4*)&Asrc_h[8];
        pa1 = *(const uint4*)&Asrc_l[8];
        pb0 = *(const uint4*)&Bsrc_h[8];
        pb1 = *(const uint4*)&Bsrc_l[8];
    }

    for (int kc = 0; kc < CH; kc++) {
        const int cur = kc & 1;
        if (kc < CH - 1) {
            *(uint4*)&S[cur ^ 1][0][0][sdst] = pa0;
            *(uint4*)&S[cur ^ 1][0][1][sdst] = pa1;
            *(uint4*)&S[cur ^ 1][1][0][sdst] = pb0;
            *(uint4*)&S[cur ^ 1][1][1][sdst] = pb1;
        }
        if (kc < CH - 2) {
            const int koff = (kc + 2) * 8;
            pa0 = *(const uint4*)&Asrc_h[koff];
            pa1 = *(const uint4*)&Asrc_l[koff];
            pb0 = *(const uint4*)&Bsrc_h[koff];
            pb1 = *(const uint4*)&Bsrc_l[koff];
        }

        const uint32_t* sAh = &S[cur][0][0][0];
        const uint32_t* sAl = &S[cur][0][1][0];
        const uint32_t* sBh = &S[cur][1][0][0];
        const uint32_t* sBl = &S[cur][1][1][0];

        uint32_t ah[4][4], al[4][4], bh[4][2], bl[4][2];
        #pragma unroll
        for (int mt = 0; mt < 4; mt++) {
            const int r0 = (warp_m * 64 + mt * 16 + g) * 12;
            const int r8 = r0 + 96;
            ah[mt][0] = sAh[r0 + tg];     ah[mt][1] = sAh[r8 + tg];
            ah[mt][2] = sAh[r0 + tg + 4]; ah[mt][3] = sAh[r8 + tg + 4];
            al[mt][0] = sAl[r0 + tg];     al[mt][1] = sAl[r8 + tg];
            al[mt][2] = sAl[r0 + tg + 4]; al[mt][3] = sAl[r8 + tg + 4];
        }
        #pragma unroll
        for (int nt = 0; nt < 4; nt++) {
            const int c0 = (warp_n * 32 + nt * 8 + g) * 12;
            bh[nt][0] = sBh[c0 + tg]; bh[nt][1] = sBh[c0 + tg + 4];
            bl[nt][0] = sBl[c0 + tg]; bl[nt][1] = sBl[c0 + tg + 4];
        }
        #pragma unroll
        for (int term = 0; term < 3; term++)
            #pragma unroll
            for (int mt = 0; mt < 4; mt++)
                #pragma unroll
                for (int nt = 0; nt < 4; nt++)
                    mma16816(acc[mt][nt],
                             (term == 2) ? al[mt] : ah[mt],
                             (term == 1) ? bl[nt] : bh[nt]);
        __syncthreads();
    }

    #pragma unroll
    for (int nt = 0; nt < 4; nt++) {
        const int col = n0 + warp_n * 32 + nt * 8 + 2 * tg;
        const float b0 = bias[col], b1 = bias[col + 1];
        float sc0, sc1, mu0, mu1, be0, be1;
        if (EPI == 2) {
            sc0 = bng[col] * rsqrtf(bnv[col] + 1e-5f);
            sc1 = bng[col + 1] * rsqrtf(bnv[col + 1] + 1e-5f);
            mu0 = bnm[col]; mu1 = bnm[col + 1];
            be0 = bnb[col]; be1 = bnb[col + 1];
        }
        #pragma unroll
        for (int mt = 0; mt < 4; mt++) {
            const size_t row = (size_t)m0 + warp_m * 64 + mt * 16 + g;
            float c0 = acc[mt][nt][0] + b0, c1 = acc[mt][nt][1] + b1;
            float c2 = acc[mt][nt][2] + b0, c3 = acc[mt][nt][3] + b1;
            if (EPI == 0) {
                *(float2*)&outf[row * LDC + col]       = make_float2(c0, c1);
                *(float2*)&outf[(row + 8) * LDC + col] = make_float2(c2, c3);
            } else if (EPI == 1) {
                float x0 = elu1(c0), x1 = elu1(c1), x2 = elu1(c2), x3 = elu1(c3);
                uint32_t hi, lo;
                split2(x0, x1, hi, lo);
                outh[row * KPO + (col >> 1)] = hi;
                outl[row * KPO + (col >> 1)] = lo;
                split2(x2, x3, hi, lo);
                outh[(row + 8) * KPO + (col >> 1)] = hi;
                outl[(row + 8) * KPO + (col >> 1)] = lo;
            } else {
                float v0 = (elu1(c0) - mu0) * sc0 + be0;
                float v1 = (elu1(c1) - mu1) * sc1 + be1;
                float v2 = (elu1(c2) - mu0) * sc0 + be0;
                float v3 = (elu1(c3) - mu1) * sc1 + be1;
                *(float2*)&outf[row * LDC + col]       = make_float2(v0, v1);
                *(float2*)&outf[(row + 8) * LDC + col] = make_float2(v2, v3);
            }
        }
    }
}

// ============================ Kernel D (occupancy: 1 channel/lane, 4 CTAs/SM) ============================
// 16 points/CTA, 4 warps per point (channel quarters), 2 points in flight, 8 passes.
constexpr int D_T = 256;
constexpr int D_WDW = 0;       // 8448 (64 x pitch132), [d*16+i][c]
constexpr int D_XF  = 8448;    // 4096 (16 x 256)
constexpr int D_SMEM = 12544;  // floats = 50176 B -> 4 CTAs/SM (smem-capped)

__global__ void __launch_bounds__(D_T, 4)
kernelD(const float* __restrict__ fts, const float* __restrict__ wdw,
        const float* __restrict__ bdw)
{
    extern __shared__ float sm[];
    float* wdwT = sm + D_WDW;
    float* Xfs  = sm + D_XF;

    const int t = threadIdx.x;
    const int pbase = blockIdx.x * 16;
    const int warp = t >> 5, lane = t & 31;

    for (int i = t; i < 8192; i += D_T) {
        int c = i >> 6, r = i & 63;           // r = d*16 + k
        wdwT[r * 132 + c] = wdw[i];
    }
    for (int i = t; i < 4096; i += D_T)
        Xfs[i] = g_Xf[(size_t)pbase * 256 + i];
    __syncthreads();

    const int wh = warp & 3;                  // channel quarter
    const int c = wh * 32 + lane;             // owned channel 0..127
    const int gofs = warp >> 2;               // 0 or 1 (2 points in flight)

    float4 bA = *(const float4*)&bdw[c * 4];

    // prefetch: warp's next point has 16 rows x 256B = 32 lines; lane -> one line
    const int pf_row = lane >> 1, pf_half = (lane & 1) * 32;

    #pragma unroll
    for (int p = 0; p < 8; p++) {
        const int g = p * 2 + gofs;
        const size_t pt = pbase + g;

        const float* src = (c < 64) ? (g_h2 + pt * 1024 + c)
                                    : (fts  + pt * 1024 + (c - 64));
        float fr[16];
        #pragma unroll
        for (int j = 0; j < 16; j++)
            fr[j] = src[j * 64];

        if (p < 7) {
            const size_t ptN = pt + 2;
            const float* baseN = (c < 64) ? (g_h2 + ptN * 1024)
                                          : (fts  + ptN * 1024 );
            l2pf(baseN + pf_row * 64 + pf_half);
        }

        float dA[4] = {bA.x, bA.y, bA.z, bA.w};

        #pragma unroll
        for (int i = 0; i < 16; i++) {
            const float* xr = &Xfs[g * 256 + i * 16];
            float4 x0 = *(const float4*)&xr[0];
            float4 x1 = *(const float4*)&xr[4];
            float4 x2 = *(const float4*)&xr[8];
            float4 x3 = *(const float4*)&xr[12];
            float fx;
            fx  = x0.x * fr[0]  + x0.y * fr[1]  + x0.z * fr[2]  + x0.w * fr[3];
            fx += x1.x * fr[4]  + x1.y * fr[5]  + x1.z * fr[6]  + x1.w * fr[7];
            fx += x2.x * fr[8]  + x2.y * fr[9]  + x2.z * fr[10] + x2.w * fr[11];
            fx += x3.x * fr[12] + x3.y * fr[13] + x3.z * fr[14] + x3.w * fr[15];

            #pragma unroll
            for (int d = 0; d < 4; d++)
                dA[d] += fx * wdwT[(d * 16 + i) * 132 + c];
        }

        uint32_t hi0, lo0, hi1, lo1;
        split2(dA[0], dA[1], hi0, lo0);
        split2(dA[2], dA[3], hi1, lo1);
        *(uint2*)&g_dwh[pt * 256 + c * 2] = make_uint2(hi0, hi1);
        *(uint2*)&g_dwl[pt * 256 + c * 2] = make_uint2(lo0, lo1);
    }
}

} // namespace

extern "C" void kernel_launch(void* const* d_in, const int* in_sizes, int n_in,
                              void* d_out, int out_size) {
    const float* rep_pt = (const float*)d_in[0];
    const float* pts    = (const float*)d_in[1];
    const float* fts    = (const float*)d_in[2];
    const float* w1     = (const float*)d_in[3];
    const float* b1     = (const float*)d_in[4];
    const float* w2     = (const float*)d_in[5];
    const float* b2     = (const float*)d_in[6];
    const float* wc1    = (const float*)d_in[7];
    const float* bc1    = (const float*)d_in[8];
    const float* wx1    = (const float*)d_in[9];
    const float* bx1    = (const float*)d_in[10];
    const float* wx2    = (const float*)d_in[11];
    const float* bx2    = (const float*)d_in[12];
    const float* wdw    = (const float*)d_in[13];
    const float* bdw    = (const float*)d_in[14];
    const float* wpw    = (const float*)d_in[15];
    const float* bpw    = (const float*)d_in[16];
    const float* bng    = (const float*)d_in[17];
    const float* bnb    = (const float*)d_in[18];
    const float* bnm    = (const float*)d_in[19];
    const float* bnv    = (const float*)d_in[20];
    float* out = (float*)d_out;

    static bool attr_done = false;
    if (!attr_done) {
        cudaFuncSetAttribute(kernelA, cudaFuncAttributeMaxDynamicSharedMemorySize,
                             A_SMEM * (int)sizeof(float));
        cudaFuncSetAttribute(kernelD, cudaFuncAttributeMaxDynamicSharedMemorySize,
                             D_SMEM * (int)sizeof(float));
        attr_done = true;
    }

    uint32_t *pX0h, *pX0l, *pX1h, *pX1l, *pdwh, *pdwl;
    uint32_t *pw1h, *pw1l, *pw2h, *pw2l, *pwph, *pwpl;
    float* pXf;
    cudaGetSymbolAddress((void**)&pX0h, g_X0h);
    cudaGetSymbolAddress((void**)&pX0l, g_X0l);
    cudaGetSymbolAddress((void**)&pX1h, g_X1h);
    cudaGetSymbolAddress((void**)&pX1l, g_X1l);
    cudaGetSymbolAddress((void**)&pXf,  g_Xf);
    cudaGetSymbolAddress((void**)&pdwh, g_dwh);
    cudaGetSymbolAddress((void**)&pdwl, g_dwl);
    cudaGetSymbolAddress((void**)&pw1h, g_wx1h);
    cudaGetSymbolAddress((void**)&pw1l, g_wx1l);
    cudaGetSymbolAddress((void**)&pw2h, g_wx2h);
    cudaGetSymbolAddress((void**)&pw2l, g_wx2l);
    cudaGetSymbolAddress((void**)&pwph, g_wpwh);
    cudaGetSymbolAddress((void**)&pwpl, g_wpwl);

    // A: h1 -> h2 (mma) + X0 (hi/lo), with fused weight conversion
    kernelA<<<NPTS / 64, A_T, A_SMEM * sizeof(float)>>>(
        rep_pt, pts, w1, b1, w2, b2, wc1, bc1, wx1, wx2, wpw);
    // B: X1 = elu(X0 @ wx1 + bx1) -> bf16 hi/lo
    bgemm<128, 2, 1><<<(NPTS / 128) * 2, 256>>>(
        pX0h, pX0l, pw1h, pw1l, bx1, nullptr, nullptr, nullptr, nullptr,
        nullptr, pX1h, pX1l);
    // C: Xf = X1 @ wx2 + bx2 -> f32
    bgemm<128, 2, 0><<<(NPTS / 128) * 2, 256>>>(
        pX1h, pX1l, pw2h, pw2l, bx2, nullptr, nullptr, nullptr, nullptr,
        pXf, nullptr, nullptr);
    // D: X-transform + depthwise -> dw bf16 hi/lo
    kernelD<<<NPTS / 16, D_T, D_SMEM * sizeof(float)>>>(fts, wdw, bdw);
    // E: out = BN(elu(dw @ wpw + bpw)) -> f32
    bgemm<256, 1, 2><<<NPTS / 128, 256>>>(
        pdwh, pdwl, pwph, pwpl, bpw, bng, bnb, bnm, bnv,
        out, nullptr, nullptr);
}